// round 11
// baseline (speedup 1.0000x reference)
#include <cuda_runtime.h>
#include <cuda_bf16.h>
#include <cstdint>

// ---------------- scratch (static device arrays; no cudaMalloc) -------------
__device__ __align__(16) __nv_bfloat16 g_Xhi[4194304], g_Xlo[4194304];
__device__ __align__(16) __nv_bfloat16 g_Whi[4][1048576], g_Wlo[4][1048576];
__device__ __align__(16) __nv_bfloat16 g_Qhi[4194304], g_Qlo[4194304];
__device__ __align__(16) __nv_bfloat16 g_Khi[4194304], g_Klo[4194304];
__device__ __align__(16) __nv_bfloat16 g_Vhi[4194304], g_Vlo[4194304]; // [bh][s][dkv]
__device__ __align__(16) __nv_bfloat16 g_Chi[4194304], g_Clo[4194304]; // [m][1024]
__device__ float g_bias[16 * 4096];

// ---------------- helpers -----------------------------------------------------
__device__ __forceinline__ uint32_t smem_u32(const void* p) {
    uint32_t a;
    asm("{ .reg .u64 t; cvta.to.shared.u64 t, %1; cvt.u32.u64 %0, t; }" : "=r"(a) : "l"(p));
    return a;
}
__device__ __forceinline__ uint32_t swz(uint32_t off) { return off ^ ((off >> 3) & 0x70); }

__device__ __forceinline__ void cpa16(uint32_t saddr, const void* g) {
    asm volatile("cp.async.cg.shared.global [%0], [%1], 16;" :: "r"(saddr), "l"(g));
}
#define CP_COMMIT() asm volatile("cp.async.commit_group;" ::: "memory")
#define CP_WAIT1()  asm volatile("cp.async.wait_group 1;" ::: "memory")
#define CP_WAIT0()  asm volatile("cp.async.wait_group 0;" ::: "memory")

__device__ __forceinline__ void ldsm4(uint32_t* r, uint32_t addr) {
    asm volatile("ldmatrix.sync.aligned.m8n8.x4.shared.b16 {%0,%1,%2,%3}, [%4];"
        : "=r"(r[0]), "=r"(r[1]), "=r"(r[2]), "=r"(r[3]) : "r"(addr));
}
__device__ __forceinline__ void ldsm4t(uint32_t* r, uint32_t addr) {
    asm volatile("ldmatrix.sync.aligned.m8n8.x4.trans.shared.b16 {%0,%1,%2,%3}, [%4];"
        : "=r"(r[0]), "=r"(r[1]), "=r"(r[2]), "=r"(r[3]) : "r"(addr));
}
__device__ __forceinline__ void mma16816(float* d, const uint32_t* a, const uint32_t* b) {
    asm volatile("mma.sync.aligned.m16n8k16.row.col.f32.bf16.bf16.f32 "
        "{%0,%1,%2,%3}, {%4,%5,%6,%7}, {%8,%9}, {%0,%1,%2,%3};"
        : "+f"(d[0]), "+f"(d[1]), "+f"(d[2]), "+f"(d[3])
        : "r"(a[0]), "r"(a[1]), "r"(a[2]), "r"(a[3]), "r"(b[0]), "r"(b[1]));
}
__device__ __forceinline__ uint32_t pk2(float a, float b, uint32_t& lo) {
    __nv_bfloat162 h, l;
    h.x = __float2bfloat16_rn(a); h.y = __float2bfloat16_rn(b);
    l.x = __float2bfloat16_rn(a - __bfloat162float(h.x));
    l.y = __float2bfloat16_rn(b - __bfloat162float(h.y));
    lo = *(uint32_t*)&l;
    return *(uint32_t*)&h;
}

// ---------------- prep kernels -------------------------------------------------
__global__ void bias_init(const float* __restrict__ rel_bias) {
    int d = blockIdx.x * 256 + threadIdx.x;
    if (d >= 4096) return;
    int n = -(d - 2048);
    int ret = 0;
    if (n < 0) { ret = 16; n = -n; }
    int bucket;
    if      (n <  8) bucket = n;
    else if (n < 12) bucket = 8;
    else if (n < 16) bucket = 9;
    else if (n < 23) bucket = 10;
    else if (n < 32) bucket = 11;
    else if (n < 46) bucket = 12;
    else if (n < 64) bucket = 13;
    else if (n < 91) bucket = 14;
    else             bucket = 15;
    bucket += ret;
    #pragma unroll
    for (int h = 0; h < 16; h++)
        g_bias[h * 4096 + d] = rel_bias[bucket * 16 + h];
}

__global__ void split_x(const float* __restrict__ src) {
    size_t i = ((size_t)blockIdx.x * 256 + threadIdx.x) * 4;
    float4 v = *(const float4*)(src + i);
    float x[4] = {v.x, v.y, v.z, v.w};
    #pragma unroll
    for (int j = 0; j < 4; j++) {
        __nv_bfloat16 hh = __float2bfloat16_rn(x[j]);
        g_Xhi[i + j] = hh;
        g_Xlo[i + j] = __float2bfloat16_rn(x[j] - __bfloat162float(hh));
    }
}

__global__ void wsplit(const float* __restrict__ W0, const float* __restrict__ W1,
                       const float* __restrict__ W2, const float* __restrict__ W3) {
    __shared__ float tile[32][33];
    const float* W = blockIdx.z == 0 ? W0 : blockIdx.z == 1 ? W1 : blockIdx.z == 2 ? W2 : W3;
    int n0 = blockIdx.x * 32, k0 = blockIdx.y * 32;
    int tx = threadIdx.x, ty = threadIdx.y;
    #pragma unroll
    for (int j = 0; j < 4; j++)
        tile[ty + j * 8][tx] = W[(size_t)(k0 + ty + j * 8) * 1024 + n0 + tx];
    __syncthreads();
    #pragma unroll
    for (int j = 0; j < 4; j++) {
        float x = tile[tx][ty + j * 8];
        __nv_bfloat16 hh = __float2bfloat16_rn(x);
        size_t o = (size_t)(n0 + ty + j * 8) * 1024 + k0 + tx;     // [n][k]
        g_Whi[blockIdx.z][o] = hh;
        g_Wlo[blockIdx.z][o] = __float2bfloat16_rn(x - __bfloat162float(hh));
    }
}

// ---------------- unified 128x128 HMMA GEMM, 3-stage pipeline, 512 thr ---------
// term-outer MMA ordering + ki-level fragment double-buffering
__global__ __launch_bounds__(512) void proj_gemm(float* __restrict__ outp, int qkv) {
    extern __shared__ __align__(1024) char smx[];
    const uint32_t sb = smem_u32(smx);
    const int t = threadIdx.x, lane = t & 31, wid = t >> 5;
    const int wm = wid >> 2, wn = wid & 3;         // 4x4 warp grid, 32x32 each
    const int m0 = blockIdx.y << 7, n0 = blockIdx.x << 7;
    const int mode = qkv ? (int)blockIdx.z : 3;
    const __nv_bfloat16* Ah = (mode == 3) ? g_Chi : g_Xhi;
    const __nv_bfloat16* Al = (mode == 3) ? g_Clo : g_Xlo;
    const __nv_bfloat16* Bh = g_Whi[mode];
    const __nv_bfloat16* Bl = g_Wlo[mode];

    auto issue = [&](int kc) {
        const int kb = kc << 6;
        const uint32_t stb = sb + (uint32_t)(kc % 3) * 65536;
        #pragma unroll
        for (int i = 0; i < 2; i++) {
            int idx = t + (i << 9);
            int row = idx >> 3, ge = (idx & 7) << 3;
            uint32_t so = swz(row * 128 + (ge << 1));
            size_t goa = (size_t)(m0 + row) * 1024 + kb + ge;
            size_t gob = (size_t)(n0 + row) * 1024 + kb + ge;
            cpa16(stb + so,         Ah + goa);
            cpa16(stb + 16384 + so, Al + goa);
            cpa16(stb + 32768 + so, Bh + gob);
            cpa16(stb + 49152 + so, Bl + gob);
        }
        CP_COMMIT();
    };

    const uint32_t a_row = (lane & 7) + ((lane >> 3) & 1) * 8;
    const uint32_t a_kb  = (lane >> 4) * 16;
    const uint32_t b_row = (lane & 7) + (lane >> 4) * 8;
    const uint32_t b_kb  = ((lane >> 3) & 1) * 16;

    float acc[2][4][4] = {};
    issue(0); issue(1);
    for (int kc = 0; kc < 16; kc++) {
        if (kc == 15) { CP_WAIT0(); } else { CP_WAIT1(); }
        __syncthreads();
        const uint32_t stb = sb + (uint32_t)(kc % 3) * 65536;

        uint32_t ahf[2][2][4], alf[2][2][4], bhf[2][2][4], blf[2][2][4];
        auto ldfrag = [&](int ki, int buf) {
            #pragma unroll
            for (int mi = 0; mi < 2; mi++) {
                uint32_t off = swz(((wm << 5) + (mi << 4) + a_row) * 128 + (ki << 5) + a_kb);
                ldsm4(ahf[buf][mi], stb + off);
                ldsm4(alf[buf][mi], stb + 16384 + off);
            }
            #pragma unroll
            for (int nh = 0; nh < 2; nh++) {
                uint32_t off = swz(((wn << 5) + (nh << 4) + b_row) * 128 + (ki << 5) + b_kb);
                ldsm4(bhf[buf][nh], stb + 32768 + off);
                ldsm4(blf[buf][nh], stb + 49152 + off);
            }
        };
        ldfrag(0, 0);
        #pragma unroll
        for (int ki = 0; ki < 4; ki++) {
            const int cur = ki & 1;
            if (ki < 3) ldfrag(ki + 1, cur ^ 1);
            // term hi*hi
            #pragma unroll
            for (int mi = 0; mi < 2; mi++)
                #pragma unroll
                for (int ni = 0; ni < 4; ni++)
                    mma16816(acc[mi][ni], ahf[cur][mi], &bhf[cur][ni >> 1][(ni & 1) << 1]);
            // term lo*hi
            #pragma unroll
            for (int mi = 0; mi < 2; mi++)
                #pragma unroll
                for (int ni = 0; ni < 4; ni++)
                    mma16816(acc[mi][ni], alf[cur][mi], &bhf[cur][ni >> 1][(ni & 1) << 1]);
            // term hi*lo
            #pragma unroll
            for (int mi = 0; mi < 2; mi++)
                #pragma unroll
                for (int ni = 0; ni < 4; ni++)
                    mma16816(acc[mi][ni], ahf[cur][mi], &blf[cur][ni >> 1][(ni & 1) << 1]);
        }
        if (kc + 2 < 16) issue(kc + 2);
    }

    const int g = lane >> 2, tq = lane & 3;
    #pragma unroll
    for (int mi = 0; mi < 2; mi++) {
        #pragma unroll
        for (int ni = 0; ni < 4; ni++) {
            #pragma unroll
            for (int half = 0; half < 2; half++) {
                int r = (wm << 5) + (mi << 4) + g + half * 8;
                int c = (wn << 5) + (ni << 3) + (tq << 1);
                float v0 = acc[mi][ni][half * 2], v1 = acc[mi][ni][half * 2 + 1];
                int m = m0 + r, n = n0 + c;
                if (mode == 3) {
                    *(float2*)&outp[(size_t)m * 1024 + n] = make_float2(v0, v1);
                } else {
                    uint32_t lo, hi = pk2(v0, v1, lo);
                    int b = m >> 11, s = m & 2047, hd = n >> 6, dk = n & 63;
                    size_t o = (((size_t)(b * 16 + hd) * 2048) + s) * 64 + dk;
                    __nv_bfloat16* dh = (mode == 0) ? g_Qhi : (mode == 1) ? g_Khi : g_Vhi;
                    __nv_bfloat16* dl = (mode == 0) ? g_Qlo : (mode == 1) ? g_Klo : g_Vlo;
                    *(uint32_t*)(dh + o) = hi;
                    *(uint32_t*)(dl + o) = lo;
                }
            }
        }
    }
}

// ---------------- fused attention: 64q-tile, two-pass softmax + PV, 512 thr ----
__global__ __launch_bounds__(512) void attn_fused(const int* __restrict__ mask,
                                                  float* __restrict__ attn) {
    extern __shared__ __align__(1024) char smx[];
    const uint32_t sb = smem_u32(smx);
    float* rowsm = (float*)(smx + 16384);
    float* rinv  = (float*)(smx + 16640);
    const int t = threadIdx.x, lane = t & 31, wid = t >> 5;
    const int wm = wid >> 2, wn = wid & 3;          // wm: q 16-row slice, wn: k 32-slice
    const int q0 = blockIdx.x << 6, bh = blockIdx.y, b = bh >> 4, h = bh & 15;
    const int g = lane >> 2, tq = lane & 3;

    // persistent Q tile (64 x 64 dkv), hi/lo — one pass with 512 threads
    {
        int row = t >> 3, ge = (t & 7) << 3;
        uint32_t so = swz(row * 128 + (ge << 1));
        size_t go = ((size_t)bh * 2048 + q0 + row) * 64 + ge;
        *(uint4*)(smx + so)        = *(const uint4*)(g_Qhi + go);
        *(uint4*)(smx + 8192 + so) = *(const uint4*)(g_Qlo + go);
    }
    if (t < 64) rowsm[t] = 0.f;
    __syncthreads();

    const uint32_t a_row = (lane & 7) + ((lane >> 3) & 1) * 8;
    const uint32_t a_kb  = (lane >> 4) * 16;
    const uint32_t b_row = (lane & 7) + (lane >> 4) * 8;
    const uint32_t b_kb  = ((lane >> 3) & 1) * 16;

    auto issue = [&](int kt, bool withV) {
        const int k0 = kt << 7, s = kt & 1;
        const uint32_t stb = sb + 20480 + (uint32_t)s * 65536;
        #pragma unroll
        for (int i = 0; i < 2; i++) {
            int idx = t + (i << 9);
            int row = idx >> 3, ge = (idx & 7) << 3;
            uint32_t so = swz(row * 128 + (ge << 1));
            size_t go = ((size_t)bh * 2048 + k0 + row) * 64 + ge;
            cpa16(stb + so,         g_Khi + go);
            cpa16(stb + 16384 + so, g_Klo + go);
            if (withV) {
                cpa16(stb + 32768 + so, g_Vhi + go);
                cpa16(stb + 49152 + so, g_Vlo + go);
            }
        }
        CP_COMMIT();
        float* bw = (float*)(smx + 17408 + s * 1024);
        int*   ms = (int*)(smx + 19456 + s * 512);
        if (t < 191) bw[t] = g_bias[h * 4096 + (k0 - q0 + 1985) + t];
        if (t < 128) ms[t] = mask[b * 2048 + k0 + t];
    };

    // hoist this warp's Q fragments (16 q-rows, k-invariant)
    uint32_t qh1[4][4], ql1[4][4];
    #pragma unroll
    for (int ki = 0; ki < 4; ki++) {
        uint32_t off = swz(((wm << 4) + a_row) * 128 + (ki << 5) + a_kb);
        ldsm4(qh1[ki], sb + off);
        ldsm4(ql1[ki], sb + 8192 + off);
    }

    // S compute with term-outer ordering (acc reuse distance 4)
    auto computeS = [&](int stage, float acc[4][4]) {
        const uint32_t kbb = sb + 20480 + (uint32_t)stage * 65536;
        #pragma unroll
        for (int ki = 0; ki < 4; ki++) {
            uint32_t bhf[2][4], blf[2][4];
            #pragma unroll
            for (int nh = 0; nh < 2; nh++) {
                uint32_t off = swz(((wn << 5) + (nh << 4) + b_row) * 128 + (ki << 5) + b_kb);
                ldsm4(bhf[nh], kbb + off);
                ldsm4(blf[nh], kbb + 16384 + off);
            }
            #pragma unroll
            for (int ni = 0; ni < 4; ni++)
                mma16816(acc[ni], qh1[ki], &bhf[ni >> 1][(ni & 1) << 1]);
            #pragma unroll
            for (int ni = 0; ni < 4; ni++)
                mma16816(acc[ni], ql1[ki], &bhf[ni >> 1][(ni & 1) << 1]);
            #pragma unroll
            for (int ni = 0; ni < 4; ni++)
                mma16816(acc[ni], qh1[ki], &blf[ni >> 1][(ni & 1) << 1]);
        }
    };

    // ---------------- pass 1: row sums ----------------
    float rowpart[2] = {};
    issue(0, false);
    for (int kt = 0; kt < 16; kt++) {
        if (kt + 1 < 16) { issue(kt + 1, false); CP_WAIT1(); }
        else             { CP_WAIT0(); }
        __syncthreads();
        float acc[4][4] = {};
        computeS(kt & 1, acc);
        const float* bw = (const float*)(smx + 17408 + (kt & 1) * 1024);
        const int*   ms = (const int*)(smx + 19456 + (kt & 1) * 512);
        #pragma unroll
        for (int half = 0; half < 2; half++) {
            int r = (wm << 4) + g + half * 8;
            float rp = 0.f;
            #pragma unroll
            for (int ni = 0; ni < 4; ni++) {
                int c = (wn << 5) + (ni << 3) + (tq << 1);
                float s0 = fmaf(acc[ni][half * 2],     0.125f, bw[c - r + 63]);
                float s1 = fmaf(acc[ni][half * 2 + 1], 0.125f, bw[c + 1 - r + 63]);
                rp += (ms[c]     ? __expf(s0) : 0.f);
                rp += (ms[c + 1] ? __expf(s1) : 0.f);
            }
            rowpart[half] += rp;
        }
        __syncthreads();
    }
    #pragma unroll
    for (int half = 0; half < 2; half++) {
        float v = rowpart[half];
        v += __shfl_xor_sync(0xffffffffu, v, 1);
        v += __shfl_xor_sync(0xffffffffu, v, 2);
        if (tq == 0)
            atomicAdd(&rowsm[(wm << 4) + g + half * 8], v);
    }
    __syncthreads();
    if (t < 64) rinv[t] = 1.0f / rowsm[t];
    __syncthreads();
    float riv[2];
    #pragma unroll
    for (int half = 0; half < 2; half++)
        riv[half] = rinv[(wm << 4) + g + half * 8];

    // ---------------- pass 2: normalized attn store + PV ----------------
    float pv[8][4] = {};
    issue(0, true);
    for (int kt = 0; kt < 16; kt++) {
        const int k0 = kt << 7;
        if (kt + 1 < 16) { issue(kt + 1, true); CP_WAIT1(); }
        else             { CP_WAIT0(); }
        __syncthreads();
        float acc[4][4] = {};
        computeS(kt & 1, acc);
        const float* bw = (const float*)(smx + 17408 + (kt & 1) * 1024);
        const int*   ms = (const int*)(smx + 19456 + (kt & 1) * 512);
        #pragma unroll
        for (int half = 0; half < 2; half++) {
            int r = (wm << 4) + g + half * 8;
            float ri = riv[half];
            #pragma unroll
            for (int ni = 0; ni < 4; ni++) {
                int c = (wn << 5) + (ni << 3) + (tq << 1);
                float s0 = fmaf(acc[ni][half * 2],     0.125f, bw[c - r + 63]);
                float s1 = fmaf(acc[ni][half * 2 + 1], 0.125f, bw[c + 1 - r + 63]);
                float e0 = (ms[c]     ? __expf(s0) : 0.f) * ri;
                float e1 = (ms[c + 1] ? __expf(s1) : 0.f) * ri;
                *(float2*)&attn[((size_t)bh * 2048 + q0 + r) * 2048 + k0 + c] =
                    make_float2(e0, e1);
                acc[ni][half * 2]     = e0;
                acc[ni][half * 2 + 1] = e1;
            }
        }
        // PV: reuse S accumulator fragments as A operands; V frags preloaded
        // 2 dvg at a time, term-outer ordering (reuse distance 4)
        const uint32_t vbase = sb + 20480 + (uint32_t)(kt & 1) * 65536 + 32768;
        #pragma unroll
        for (int j = 0; j < 2; j++) {
            uint32_t Ahh[4], All[4];
            Ahh[0] = pk2(acc[2*j][0],   acc[2*j][1],   All[0]);
            Ahh[1] = pk2(acc[2*j][2],   acc[2*j][3],   All[1]);
            Ahh[2] = pk2(acc[2*j+1][0], acc[2*j+1][1], All[2]);
            Ahh[3] = pk2(acc[2*j+1][2], acc[2*j+1][3], All[3]);
            #pragma unroll
            for (int dp = 0; dp < 2; dp++) {          // dvg pairs {0,1},{2,3}
                uint32_t vh[2][4], vl[2][4];
                #pragma unroll
                for (int dd = 0; dd < 2; dd++) {
                    int dvg = (dp << 1) + dd;
                    uint32_t off = swz(((wn << 5) + (j << 4) + a_row) * 128 + (dvg << 5) + a_kb);
                    ldsm4t(vh[dd], vbase + off);
                    ldsm4t(vl[dd], vbase + 16384 + off);
                }
                #pragma unroll
                for (int dd = 0; dd < 2; dd++)
                    #pragma unroll
                    for (int n8 = 0; n8 < 2; n8++)
                        mma16816(pv[((dp << 1) + dd) * 2 + n8], Ahh, &vh[dd][n8 << 1]);
                #pragma unroll
                for (int dd = 0; dd < 2; dd++)
                    #pragma unroll
                    for (int n8 = 0; n8 < 2; n8++)
                        mma16816(pv[((dp << 1) + dd) * 2 + n8], All, &vh[dd][n8 << 1]);
                #pragma unroll
                for (int dd = 0; dd < 2; dd++)
                    #pragma unroll
                    for (int n8 = 0; n8 < 2; n8++)
                        mma16816(pv[((dp << 1) + dd) * 2 + n8], Ahh, &vl[dd][n8 << 1]);
            }
        }
        __syncthreads();
    }

    // ---------------- cross-warp PV reduction + ctx store ----------------
    #pragma unroll
    for (int ni = 0; ni < 8; ni++)
        #pragma unroll
        for (int half = 0; half < 2; half++) {
            int row = (wm << 4) + g + half * 8;
            uint32_t off = 20480 + (uint32_t)wn * 16384 + row * 256 + ((ni << 3) + (tq << 1)) * 4;
            *(float2*)(smx + off) = make_float2(pv[ni][half * 2], pv[ni][half * 2 + 1]);
        }
    __syncthreads();
    #pragma unroll
    for (int i = 0; i < 4; i++) {
        int idx = t + (i << 9);
        int row = idx >> 5, dvp = idx & 31;
        float sx = 0.f, sy = 0.f;
        #pragma unroll
        for (int w = 0; w < 4; w++) {
            float2 v = *(float2*)(smx + 20480 + w * 16384 + row * 256 + dvp * 8);
            sx += v.x; sy += v.y;
        }
        uint32_t lo, hi = pk2(sx, sy, lo);
        size_t o = ((size_t)(b * 2048 + q0 + row)) * 1024 + (h << 6) + dvp * 2;
        *(uint32_t*)(g_Chi + o) = hi;
        *(uint32_t*)(g_Clo + o) = lo;
    }
}

// ---------------- launch --------------------------------------------------------
#define PROJ_SMEM 196608
#define ATT_SMEM  151552

extern "C" void kernel_launch(void* const* d_in, const int* in_sizes, int n_in,
                              void* d_out, int out_size) {
    const float* hs   = (const float*)d_in[0];
    const int*   mask = (const int*)d_in[1];
    const float* Wq   = (const float*)d_in[2];
    const float* Wk   = (const float*)d_in[3];
    const float* Wv   = (const float*)d_in[4];
    const float* Wo   = (const float*)d_in[5];
    const float* rb   = (const float*)d_in[6];
    float* out  = (float*)d_out;
    float* attn = out + 4194304;

    cudaFuncSetAttribute(proj_gemm,  cudaFuncAttributeMaxDynamicSharedMemorySize, PROJ_SMEM);
    cudaFuncSetAttribute(attn_fused, cudaFuncAttributeMaxDynamicSharedMemorySize, ATT_SMEM);

    bias_init<<<16, 256>>>(rb);
    split_x<<<4096, 256>>>(hs);
    wsplit<<<dim3(32, 32, 4), dim3(32, 8)>>>(Wq, Wk, Wv, Wo);

    proj_gemm<<<dim3(8, 32, 3), 512, PROJ_SMEM>>>(nullptr, 1);   // Q,K,V fused

    attn_fused<<<dim3(32, 32), 512, ATT_SMEM>>>(mask, attn);     // softmax+attn+ctx

    proj_gemm<<<dim3(8, 32, 1), 512, PROJ_SMEM>>>(out, 0);       // ctx @ Wo
}

// round 12
// speedup vs baseline: 1.0693x; 1.0693x over previous
#include <cuda_runtime.h>
#include <cuda_bf16.h>
#include <cstdint>

// ---------------- scratch (static device arrays; no cudaMalloc) -------------
__device__ __align__(16) __nv_bfloat16 g_Xhi[4194304], g_Xlo[4194304];
__device__ __align__(16) __nv_bfloat16 g_Whi[4][1048576], g_Wlo[4][1048576];
__device__ __align__(16) __nv_bfloat16 g_Qhi[4194304], g_Qlo[4194304];
__device__ __align__(16) __nv_bfloat16 g_Khi[4194304], g_Klo[4194304];
__device__ __align__(16) __nv_bfloat16 g_Vhi[4194304], g_Vlo[4194304]; // [bh][s][dkv]
__device__ __align__(16) __nv_bfloat16 g_Chi[4194304], g_Clo[4194304]; // [m][1024]
__device__ float g_bias[16 * 4096];

// ---------------- helpers -----------------------------------------------------
__device__ __forceinline__ uint32_t smem_u32(const void* p) {
    uint32_t a;
    asm("{ .reg .u64 t; cvta.to.shared.u64 t, %1; cvt.u32.u64 %0, t; }" : "=r"(a) : "l"(p));
    return a;
}
__device__ __forceinline__ uint32_t swz(uint32_t off) { return off ^ ((off >> 3) & 0x70); }

__device__ __forceinline__ void cpa16(uint32_t saddr, const void* g) {
    asm volatile("cp.async.cg.shared.global [%0], [%1], 16;" :: "r"(saddr), "l"(g));
}
#define CP_COMMIT() asm volatile("cp.async.commit_group;" ::: "memory")
#define CP_WAIT1()  asm volatile("cp.async.wait_group 1;" ::: "memory")
#define CP_WAIT0()  asm volatile("cp.async.wait_group 0;" ::: "memory")

__device__ __forceinline__ void ldsm4(uint32_t* r, uint32_t addr) {
    asm volatile("ldmatrix.sync.aligned.m8n8.x4.shared.b16 {%0,%1,%2,%3}, [%4];"
        : "=r"(r[0]), "=r"(r[1]), "=r"(r[2]), "=r"(r[3]) : "r"(addr));
}
__device__ __forceinline__ void ldsm4t(uint32_t* r, uint32_t addr) {
    asm volatile("ldmatrix.sync.aligned.m8n8.x4.trans.shared.b16 {%0,%1,%2,%3}, [%4];"
        : "=r"(r[0]), "=r"(r[1]), "=r"(r[2]), "=r"(r[3]) : "r"(addr));
}
__device__ __forceinline__ void mma16816(float* d, const uint32_t* a, const uint32_t* b) {
    asm volatile("mma.sync.aligned.m16n8k16.row.col.f32.bf16.bf16.f32 "
        "{%0,%1,%2,%3}, {%4,%5,%6,%7}, {%8,%9}, {%0,%1,%2,%3};"
        : "+f"(d[0]), "+f"(d[1]), "+f"(d[2]), "+f"(d[3])
        : "r"(a[0]), "r"(a[1]), "r"(a[2]), "r"(a[3]), "r"(b[0]), "r"(b[1]));
}
__device__ __forceinline__ uint32_t pk2(float a, float b, uint32_t& lo) {
    __nv_bfloat162 h, l;
    h.x = __float2bfloat16_rn(a); h.y = __float2bfloat16_rn(b);
    l.x = __float2bfloat16_rn(a - __bfloat162float(h.x));
    l.y = __float2bfloat16_rn(b - __bfloat162float(h.y));
    lo = *(uint32_t*)&l;
    return *(uint32_t*)&h;
}

// ---------------- prep kernels -------------------------------------------------
__global__ void bias_init(const float* __restrict__ rel_bias) {
    int d = blockIdx.x * 256 + threadIdx.x;
    if (d >= 4096) return;
    int n = -(d - 2048);
    int ret = 0;
    if (n < 0) { ret = 16; n = -n; }
    int bucket;
    if      (n <  8) bucket = n;
    else if (n < 12) bucket = 8;
    else if (n < 16) bucket = 9;
    else if (n < 23) bucket = 10;
    else if (n < 32) bucket = 11;
    else if (n < 46) bucket = 12;
    else if (n < 64) bucket = 13;
    else if (n < 91) bucket = 14;
    else             bucket = 15;
    bucket += ret;
    #pragma unroll
    for (int h = 0; h < 16; h++)
        g_bias[h * 4096 + d] = rel_bias[bucket * 16 + h];
}

__global__ void split_x(const float* __restrict__ src) {
    size_t i = ((size_t)blockIdx.x * 256 + threadIdx.x) * 4;
    float4 v = *(const float4*)(src + i);
    float x[4] = {v.x, v.y, v.z, v.w};
    #pragma unroll
    for (int j = 0; j < 4; j++) {
        __nv_bfloat16 hh = __float2bfloat16_rn(x[j]);
        g_Xhi[i + j] = hh;
        g_Xlo[i + j] = __float2bfloat16_rn(x[j] - __bfloat162float(hh));
    }
}

__global__ void wsplit(const float* __restrict__ W0, const float* __restrict__ W1,
                       const float* __restrict__ W2, const float* __restrict__ W3) {
    __shared__ float tile[32][33];
    const float* W = blockIdx.z == 0 ? W0 : blockIdx.z == 1 ? W1 : blockIdx.z == 2 ? W2 : W3;
    int n0 = blockIdx.x * 32, k0 = blockIdx.y * 32;
    int tx = threadIdx.x, ty = threadIdx.y;
    #pragma unroll
    for (int j = 0; j < 4; j++)
        tile[ty + j * 8][tx] = W[(size_t)(k0 + ty + j * 8) * 1024 + n0 + tx];
    __syncthreads();
    #pragma unroll
    for (int j = 0; j < 4; j++) {
        float x = tile[tx][ty + j * 8];
        __nv_bfloat16 hh = __float2bfloat16_rn(x);
        size_t o = (size_t)(n0 + ty + j * 8) * 1024 + k0 + tx;     // [n][k]
        g_Whi[blockIdx.z][o] = hh;
        g_Wlo[blockIdx.z][o] = __float2bfloat16_rn(x - __bfloat162float(hh));
    }
}

// ---------------- unified 128x128 HMMA GEMM, 3-stage pipeline, 512 thr ---------
__global__ __launch_bounds__(512) void proj_gemm(float* __restrict__ outp, int qkv) {
    extern __shared__ __align__(1024) char smx[];
    const uint32_t sb = smem_u32(smx);
    const int t = threadIdx.x, lane = t & 31, wid = t >> 5;
    const int wm = wid >> 2, wn = wid & 3;         // 4x4 warp grid, 32x32 each
    const int m0 = blockIdx.y << 7, n0 = blockIdx.x << 7;
    const int mode = qkv ? (int)blockIdx.z : 3;
    const __nv_bfloat16* Ah = (mode == 3) ? g_Chi : g_Xhi;
    const __nv_bfloat16* Al = (mode == 3) ? g_Clo : g_Xlo;
    const __nv_bfloat16* Bh = g_Whi[mode];
    const __nv_bfloat16* Bl = g_Wlo[mode];

    auto issue = [&](int kc) {
        const int kb = kc << 6;
        const uint32_t stb = sb + (uint32_t)(kc % 3) * 65536;
        #pragma unroll
        for (int i = 0; i < 2; i++) {
            int idx = t + (i << 9);
            int row = idx >> 3, ge = (idx & 7) << 3;
            uint32_t so = swz(row * 128 + (ge << 1));
            size_t goa = (size_t)(m0 + row) * 1024 + kb + ge;
            size_t gob = (size_t)(n0 + row) * 1024 + kb + ge;
            cpa16(stb + so,         Ah + goa);
            cpa16(stb + 16384 + so, Al + goa);
            cpa16(stb + 32768 + so, Bh + gob);
            cpa16(stb + 49152 + so, Bl + gob);
        }
        CP_COMMIT();
    };

    const uint32_t a_row = (lane & 7) + ((lane >> 3) & 1) * 8;
    const uint32_t a_kb  = (lane >> 4) * 16;
    const uint32_t b_row = (lane & 7) + (lane >> 4) * 8;
    const uint32_t b_kb  = ((lane >> 3) & 1) * 16;

    float acc[2][4][4] = {};
    issue(0); issue(1);
    for (int kc = 0; kc < 16; kc++) {
        if (kc == 15) { CP_WAIT0(); } else { CP_WAIT1(); }
        __syncthreads();
        const uint32_t stb = sb + (uint32_t)(kc % 3) * 65536;
        #pragma unroll
        for (int ki = 0; ki < 4; ki++) {
            uint32_t ahf[2][4], alf[2][4], bhf[2][4], blf[2][4];
            #pragma unroll
            for (int mi = 0; mi < 2; mi++) {
                uint32_t off = swz(((wm << 5) + (mi << 4) + a_row) * 128 + (ki << 5) + a_kb);
                ldsm4(ahf[mi], stb + off);
                ldsm4(alf[mi], stb + 16384 + off);
            }
            #pragma unroll
            for (int nh = 0; nh < 2; nh++) {
                uint32_t off = swz(((wn << 5) + (nh << 4) + b_row) * 128 + (ki << 5) + b_kb);
                ldsm4(bhf[nh], stb + 32768 + off);
                ldsm4(blf[nh], stb + 49152 + off);
            }
            #pragma unroll
            for (int mi = 0; mi < 2; mi++)
                #pragma unroll
                for (int ni = 0; ni < 4; ni++) {
                    const uint32_t* bh2 = &bhf[ni >> 1][(ni & 1) << 1];
                    const uint32_t* bl2 = &blf[ni >> 1][(ni & 1) << 1];
                    mma16816(acc[mi][ni], ahf[mi], bh2);
                    mma16816(acc[mi][ni], alf[mi], bh2);
                    mma16816(acc[mi][ni], ahf[mi], bl2);
                }
        }
        if (kc + 2 < 16) issue(kc + 2);
    }

    const int g = lane >> 2, tq = lane & 3;
    #pragma unroll
    for (int mi = 0; mi < 2; mi++) {
        #pragma unroll
        for (int ni = 0; ni < 4; ni++) {
            #pragma unroll
            for (int half = 0; half < 2; half++) {
                int r = (wm << 5) + (mi << 4) + g + half * 8;
                int c = (wn << 5) + (ni << 3) + (tq << 1);
                float v0 = acc[mi][ni][half * 2], v1 = acc[mi][ni][half * 2 + 1];
                int m = m0 + r, n = n0 + c;
                if (mode == 3) {
                    *(float2*)&outp[(size_t)m * 1024 + n] = make_float2(v0, v1);
                } else {
                    uint32_t lo, hi = pk2(v0, v1, lo);
                    int b = m >> 11, s = m & 2047, hd = n >> 6, dk = n & 63;
                    size_t o = (((size_t)(b * 16 + hd) * 2048) + s) * 64 + dk;
                    __nv_bfloat16* dh = (mode == 0) ? g_Qhi : (mode == 1) ? g_Khi : g_Vhi;
                    __nv_bfloat16* dl = (mode == 0) ? g_Qlo : (mode == 1) ? g_Klo : g_Vlo;
                    *(uint32_t*)(dh + o) = hi;
                    *(uint32_t*)(dl + o) = lo;
                }
            }
        }
    }
}

// ---------------- fused attention: 64q-tile, two-pass softmax + PV, 512 thr ----
// pass 1 uses 1-term bf16 S (row sums tolerate ~2e-4); pass 2 full 3-term.
__global__ __launch_bounds__(512) void attn_fused(const int* __restrict__ mask,
                                                  float* __restrict__ attn) {
    extern __shared__ __align__(1024) char smx[];
    const uint32_t sb = smem_u32(smx);
    float* rowsm = (float*)(smx + 16384);
    float* rinv  = (float*)(smx + 16640);
    const int t = threadIdx.x, lane = t & 31, wid = t >> 5;
    const int wm = wid >> 2, wn = wid & 3;          // wm: q 16-row slice, wn: k 32-slice
    const int q0 = blockIdx.x << 6, bh = blockIdx.y, b = bh >> 4, h = bh & 15;
    const int g = lane >> 2, tq = lane & 3;

    // persistent Q tile (64 x 64 dkv), hi/lo — one pass with 512 threads
    {
        int row = t >> 3, ge = (t & 7) << 3;
        uint32_t so = swz(row * 128 + (ge << 1));
        size_t go = ((size_t)bh * 2048 + q0 + row) * 64 + ge;
        *(uint4*)(smx + so)        = *(const uint4*)(g_Qhi + go);
        *(uint4*)(smx + 8192 + so) = *(const uint4*)(g_Qlo + go);
    }
    if (t < 64) rowsm[t] = 0.f;
    __syncthreads();

    const uint32_t a_row = (lane & 7) + ((lane >> 3) & 1) * 8;
    const uint32_t a_kb  = (lane >> 4) * 16;
    const uint32_t b_row = (lane & 7) + (lane >> 4) * 8;
    const uint32_t b_kb  = ((lane >> 3) & 1) * 16;

    // lvl: 0 = KH only (pass 1), 1 = KH+KL+VH+VL (pass 2)
    auto issue = [&](int kt, int lvl) {
        const int k0 = kt << 7, s = kt & 1;
        const uint32_t stb = sb + 20480 + (uint32_t)s * 65536;
        #pragma unroll
        for (int i = 0; i < 2; i++) {
            int idx = t + (i << 9);
            int row = idx >> 3, ge = (idx & 7) << 3;
            uint32_t so = swz(row * 128 + (ge << 1));
            size_t go = ((size_t)bh * 2048 + k0 + row) * 64 + ge;
            cpa16(stb + so, g_Khi + go);
            if (lvl) {
                cpa16(stb + 16384 + so, g_Klo + go);
                cpa16(stb + 32768 + so, g_Vhi + go);
                cpa16(stb + 49152 + so, g_Vlo + go);
            }
        }
        CP_COMMIT();
        float* bw = (float*)(smx + 17408 + s * 1024);
        int*   ms = (int*)(smx + 19456 + s * 512);
        if (t < 191) bw[t] = g_bias[h * 4096 + (k0 - q0 + 1985) + t];
        if (t < 128) ms[t] = mask[b * 2048 + k0 + t];
    };

    // hoist this warp's Q fragments (16 q-rows, k-invariant)
    uint32_t qh1[4][4], ql1[4][4];
    #pragma unroll
    for (int ki = 0; ki < 4; ki++) {
        uint32_t off = swz(((wm << 4) + a_row) * 128 + (ki << 5) + a_kb);
        ldsm4(qh1[ki], sb + off);
        ldsm4(ql1[ki], sb + 8192 + off);
    }

    // ---------------- pass 1: row sums (1-term bf16 S) ----------------
    float rowpart[2] = {};
    issue(0, 0);
    for (int kt = 0; kt < 16; kt++) {
        if (kt + 1 < 16) { issue(kt + 1, 0); CP_WAIT1(); }
        else             { CP_WAIT0(); }
        __syncthreads();
        const uint32_t kbb = sb + 20480 + (uint32_t)(kt & 1) * 65536;
        float acc[4][4] = {};
        #pragma unroll
        for (int ki = 0; ki < 4; ki++) {
            uint32_t bhf[2][4];
            #pragma unroll
            for (int nh = 0; nh < 2; nh++) {
                uint32_t off = swz(((wn << 5) + (nh << 4) + b_row) * 128 + (ki << 5) + b_kb);
                ldsm4(bhf[nh], kbb + off);
            }
            #pragma unroll
            for (int ni = 0; ni < 4; ni++)
                mma16816(acc[ni], qh1[ki], &bhf[ni >> 1][(ni & 1) << 1]);
        }
        const float* bw = (const float*)(smx + 17408 + (kt & 1) * 1024);
        const int*   ms = (const int*)(smx + 19456 + (kt & 1) * 512);
        #pragma unroll
        for (int half = 0; half < 2; half++) {
            int r = (wm << 4) + g + half * 8;
            float rp = 0.f;
            #pragma unroll
            for (int ni = 0; ni < 4; ni++) {
                int c = (wn << 5) + (ni << 3) + (tq << 1);
                float s0 = fmaf(acc[ni][half * 2],     0.125f, bw[c - r + 63]);
                float s1 = fmaf(acc[ni][half * 2 + 1], 0.125f, bw[c + 1 - r + 63]);
                rp += (ms[c]     ? __expf(s0) : 0.f);
                rp += (ms[c + 1] ? __expf(s1) : 0.f);
            }
            rowpart[half] += rp;
        }
        __syncthreads();
    }
    #pragma unroll
    for (int half = 0; half < 2; half++) {
        float v = rowpart[half];
        v += __shfl_xor_sync(0xffffffffu, v, 1);
        v += __shfl_xor_sync(0xffffffffu, v, 2);
        if (tq == 0)
            atomicAdd(&rowsm[(wm << 4) + g + half * 8], v);
    }
    __syncthreads();
    if (t < 64) rinv[t] = 1.0f / rowsm[t];
    __syncthreads();
    float riv[2];
    #pragma unroll
    for (int half = 0; half < 2; half++)
        riv[half] = rinv[(wm << 4) + g + half * 8];

    // ---------------- pass 2: normalized attn store + PV (3-term) ----------------
    float pv[8][4] = {};
    issue(0, 1);
    for (int kt = 0; kt < 16; kt++) {
        const int k0 = kt << 7;
        if (kt + 1 < 16) { issue(kt + 1, 1); CP_WAIT1(); }
        else             { CP_WAIT0(); }
        __syncthreads();
        const uint32_t kbb = sb + 20480 + (uint32_t)(kt & 1) * 65536;
        float acc[4][4] = {};
        #pragma unroll
        for (int ki = 0; ki < 4; ki++) {
            uint32_t bhf[2][4], blf[2][4];
            #pragma unroll
            for (int nh = 0; nh < 2; nh++) {
                uint32_t off = swz(((wn << 5) + (nh << 4) + b_row) * 128 + (ki << 5) + b_kb);
                ldsm4(bhf[nh], kbb + off);
                ldsm4(blf[nh], kbb + 16384 + off);
            }
            #pragma unroll
            for (int ni = 0; ni < 4; ni++) {
                const uint32_t* bh2 = &bhf[ni >> 1][(ni & 1) << 1];
                const uint32_t* bl2 = &blf[ni >> 1][(ni & 1) << 1];
                mma16816(acc[ni], qh1[ki], bh2);
                mma16816(acc[ni], ql1[ki], bh2);
                mma16816(acc[ni], qh1[ki], bl2);
            }
        }
        const float* bw = (const float*)(smx + 17408 + (kt & 1) * 1024);
        const int*   ms = (const int*)(smx + 19456 + (kt & 1) * 512);
        #pragma unroll
        for (int half = 0; half < 2; half++) {
            int r = (wm << 4) + g + half * 8;
            float ri = riv[half];
            #pragma unroll
            for (int ni = 0; ni < 4; ni++) {
                int c = (wn << 5) + (ni << 3) + (tq << 1);
                float s0 = fmaf(acc[ni][half * 2],     0.125f, bw[c - r + 63]);
                float s1 = fmaf(acc[ni][half * 2 + 1], 0.125f, bw[c + 1 - r + 63]);
                float e0 = (ms[c]     ? __expf(s0) : 0.f) * ri;
                float e1 = (ms[c + 1] ? __expf(s1) : 0.f) * ri;
                *(float2*)&attn[((size_t)bh * 2048 + q0 + r) * 2048 + k0 + c] =
                    make_float2(e0, e1);
                acc[ni][half * 2]     = e0;
                acc[ni][half * 2 + 1] = e1;
            }
        }
        // PV: reuse S accumulator fragments as A operands (m16k16)
        const uint32_t vbase = sb + 20480 + (uint32_t)(kt & 1) * 65536 + 32768;
        #pragma unroll
        for (int j = 0; j < 2; j++) {
            uint32_t Ah[4], Al[4];
            Ah[0] = pk2(acc[2*j][0],   acc[2*j][1],   Al[0]);
            Ah[1] = pk2(acc[2*j][2],   acc[2*j][3],   Al[1]);
            Ah[2] = pk2(acc[2*j+1][0], acc[2*j+1][1], Al[2]);
            Ah[3] = pk2(acc[2*j+1][2], acc[2*j+1][3], Al[3]);
            #pragma unroll
            for (int dvg = 0; dvg < 4; dvg++) {
                uint32_t bhf[4], blf[4];
                uint32_t off = swz(((wn << 5) + (j << 4) + a_row) * 128 + (dvg << 5) + a_kb);
                ldsm4t(bhf, vbase + off);
                ldsm4t(blf, vbase + 16384 + off);
                #pragma unroll
                for (int n8 = 0; n8 < 2; n8++) {
                    float* d = pv[dvg * 2 + n8];
                    mma16816(d, Ah, &bhf[n8 << 1]);
                    mma16816(d, Al, &bhf[n8 << 1]);
                    mma16816(d, Ah, &blf[n8 << 1]);
                }
            }
        }
        __syncthreads();
    }

    // ---------------- cross-warp PV reduction + ctx store ----------------
    #pragma unroll
    for (int ni = 0; ni < 8; ni++)
        #pragma unroll
        for (int half = 0; half < 2; half++) {
            int row = (wm << 4) + g + half * 8;
            uint32_t off = 20480 + (uint32_t)wn * 16384 + row * 256 + ((ni << 3) + (tq << 1)) * 4;
            *(float2*)(smx + off) = make_float2(pv[ni][half * 2], pv[ni][half * 2 + 1]);
        }
    __syncthreads();
    #pragma unroll
    for (int i = 0; i < 4; i++) {
        int idx = t + (i << 9);
        int row = idx >> 5, dvp = idx & 31;
        float sx = 0.f, sy = 0.f;
        #pragma unroll
        for (int w = 0; w < 4; w++) {
            float2 v = *(float2*)(smx + 20480 + w * 16384 + row * 256 + dvp * 8);
            sx += v.x; sy += v.y;
        }
        uint32_t lo, hi = pk2(sx, sy, lo);
        size_t o = ((size_t)(b * 2048 + q0 + row)) * 1024 + (h << 6) + dvp * 2;
        *(uint32_t*)(g_Chi + o) = hi;
        *(uint32_t*)(g_Clo + o) = lo;
    }
}

// ---------------- launch --------------------------------------------------------
#define PROJ_SMEM 196608
#define ATT_SMEM  151552

extern "C" void kernel_launch(void* const* d_in, const int* in_sizes, int n_in,
                              void* d_out, int out_size) {
    const float* hs   = (const float*)d_in[0];
    const int*   mask = (const int*)d_in[1];
    const float* Wq   = (const float*)d_in[2];
    const float* Wk   = (const float*)d_in[3];
    const float* Wv   = (const float*)d_in[4];
    const float* Wo   = (const float*)d_in[5];
    const float* rb   = (const float*)d_in[6];
    float* out  = (float*)d_out;
    float* attn = out + 4194304;

    cudaFuncSetAttribute(proj_gemm,  cudaFuncAttributeMaxDynamicSharedMemorySize, PROJ_SMEM);
    cudaFuncSetAttribute(attn_fused, cudaFuncAttributeMaxDynamicSharedMemorySize, ATT_SMEM);

    bias_init<<<16, 256>>>(rb);
    split_x<<<4096, 256>>>(hs);
    wsplit<<<dim3(32, 32, 4), dim3(32, 8)>>>(Wq, Wk, Wv, Wo);

    proj_gemm<<<dim3(8, 32, 3), 512, PROJ_SMEM>>>(nullptr, 1);   // Q,K,V fused

    attn_fused<<<dim3(32, 32), 512, ATT_SMEM>>>(mask, attn);     // softmax+attn+ctx

    proj_gemm<<<dim3(8, 32, 1), 512, PROJ_SMEM>>>(out, 0);       // ctx @ Wo
}

// round 13
// speedup vs baseline: 1.1427x; 1.0687x over previous
#include <cuda_runtime.h>
#include <cuda_bf16.h>
#include <cuda_fp16.h>
#include <cstdint>

// ---------------- scratch (static device arrays; no cudaMalloc) -------------
__device__ __align__(16) __nv_bfloat16 g_Xhi[4194304], g_Xlo[4194304];
__device__ __align__(16) __nv_bfloat16 g_Whi[4][1048576], g_Wlo[4][1048576];
__device__ __align__(16) __nv_bfloat16 g_Qhi[4194304], g_Qlo[4194304];
__device__ __align__(16) __nv_bfloat16 g_Khi[4194304], g_Klo[4194304];
__device__ __align__(16) __half g_Qf16[4194304], g_Kf16[4194304], g_V16[4194304];
__device__ __align__(16) __nv_bfloat16 g_Chi[4194304], g_Clo[4194304]; // [m][1024]
__device__ float g_bias[16 * 4096];

// ---------------- helpers -----------------------------------------------------
__device__ __forceinline__ uint32_t smem_u32(const void* p) {
    uint32_t a;
    asm("{ .reg .u64 t; cvta.to.shared.u64 t, %1; cvt.u32.u64 %0, t; }" : "=r"(a) : "l"(p));
    return a;
}
__device__ __forceinline__ uint32_t swz(uint32_t off) { return off ^ ((off >> 3) & 0x70); }

__device__ __forceinline__ void cpa16(uint32_t saddr, const void* g) {
    asm volatile("cp.async.cg.shared.global [%0], [%1], 16;" :: "r"(saddr), "l"(g));
}
#define CP_COMMIT() asm volatile("cp.async.commit_group;" ::: "memory")
#define CP_WAIT1()  asm volatile("cp.async.wait_group 1;" ::: "memory")
#define CP_WAIT0()  asm volatile("cp.async.wait_group 0;" ::: "memory")

__device__ __forceinline__ void ldsm4(uint32_t* r, uint32_t addr) {
    asm volatile("ldmatrix.sync.aligned.m8n8.x4.shared.b16 {%0,%1,%2,%3}, [%4];"
        : "=r"(r[0]), "=r"(r[1]), "=r"(r[2]), "=r"(r[3]) : "r"(addr));
}
__device__ __forceinline__ void ldsm4t(uint32_t* r, uint32_t addr) {
    asm volatile("ldmatrix.sync.aligned.m8n8.x4.trans.shared.b16 {%0,%1,%2,%3}, [%4];"
        : "=r"(r[0]), "=r"(r[1]), "=r"(r[2]), "=r"(r[3]) : "r"(addr));
}
__device__ __forceinline__ void mma16816(float* d, const uint32_t* a, const uint32_t* b) {
    asm volatile("mma.sync.aligned.m16n8k16.row.col.f32.bf16.bf16.f32 "
        "{%0,%1,%2,%3}, {%4,%5,%6,%7}, {%8,%9}, {%0,%1,%2,%3};"
        : "+f"(d[0]), "+f"(d[1]), "+f"(d[2]), "+f"(d[3])
        : "r"(a[0]), "r"(a[1]), "r"(a[2]), "r"(a[3]), "r"(b[0]), "r"(b[1]));
}
__device__ __forceinline__ void mma16816h(float* d, const uint32_t* a, const uint32_t* b) {
    asm volatile("mma.sync.aligned.m16n8k16.row.col.f32.f16.f16.f32 "
        "{%0,%1,%2,%3}, {%4,%5,%6,%7}, {%8,%9}, {%0,%1,%2,%3};"
        : "+f"(d[0]), "+f"(d[1]), "+f"(d[2]), "+f"(d[3])
        : "r"(a[0]), "r"(a[1]), "r"(a[2]), "r"(a[3]), "r"(b[0]), "r"(b[1]));
}
__device__ __forceinline__ uint32_t pk2(float a, float b, uint32_t& lo) {
    __nv_bfloat162 h, l;
    h.x = __float2bfloat16_rn(a); h.y = __float2bfloat16_rn(b);
    l.x = __float2bfloat16_rn(a - __bfloat162float(h.x));
    l.y = __float2bfloat16_rn(b - __bfloat162float(h.y));
    lo = *(uint32_t*)&l;
    return *(uint32_t*)&h;
}
__device__ __forceinline__ uint32_t h2(float a, float b) {
    __half2 h = __floats2half2_rn(a, b);
    return *(uint32_t*)&h;
}

// ---------------- prep kernels -------------------------------------------------
__global__ void bias_init(const float* __restrict__ rel_bias) {
    int d = blockIdx.x * 256 + threadIdx.x;
    if (d >= 4096) return;
    int n = -(d - 2048);
    int ret = 0;
    if (n < 0) { ret = 16; n = -n; }
    int bucket;
    if      (n <  8) bucket = n;
    else if (n < 12) bucket = 8;
    else if (n < 16) bucket = 9;
    else if (n < 23) bucket = 10;
    else if (n < 32) bucket = 11;
    else if (n < 46) bucket = 12;
    else if (n < 64) bucket = 13;
    else if (n < 91) bucket = 14;
    else             bucket = 15;
    bucket += ret;
    #pragma unroll
    for (int h = 0; h < 16; h++)
        g_bias[h * 4096 + d] = rel_bias[bucket * 16 + h];
}

__global__ void split_x(const float* __restrict__ src) {
    size_t i = ((size_t)blockIdx.x * 256 + threadIdx.x) * 4;
    float4 v = *(const float4*)(src + i);
    float x[4] = {v.x, v.y, v.z, v.w};
    #pragma unroll
    for (int j = 0; j < 4; j++) {
        __nv_bfloat16 hh = __float2bfloat16_rn(x[j]);
        g_Xhi[i + j] = hh;
        g_Xlo[i + j] = __float2bfloat16_rn(x[j] - __bfloat162float(hh));
    }
}

__global__ void wsplit(const float* __restrict__ W0, const float* __restrict__ W1,
                       const float* __restrict__ W2, const float* __restrict__ W3) {
    __shared__ float tile[32][33];
    const float* W = blockIdx.z == 0 ? W0 : blockIdx.z == 1 ? W1 : blockIdx.z == 2 ? W2 : W3;
    int n0 = blockIdx.x * 32, k0 = blockIdx.y * 32;
    int tx = threadIdx.x, ty = threadIdx.y;
    #pragma unroll
    for (int j = 0; j < 4; j++)
        tile[ty + j * 8][tx] = W[(size_t)(k0 + ty + j * 8) * 1024 + n0 + tx];
    __syncthreads();
    #pragma unroll
    for (int j = 0; j < 4; j++) {
        float x = tile[tx][ty + j * 8];
        __nv_bfloat16 hh = __float2bfloat16_rn(x);
        size_t o = (size_t)(n0 + ty + j * 8) * 1024 + k0 + tx;     // [n][k]
        g_Whi[blockIdx.z][o] = hh;
        g_Wlo[blockIdx.z][o] = __float2bfloat16_rn(x - __bfloat162float(hh));
    }
}

// ---------------- unified 128x128 HMMA GEMM, 3-stage pipeline, 512 thr ---------
__global__ __launch_bounds__(512) void proj_gemm(float* __restrict__ outp, int qkv) {
    extern __shared__ __align__(1024) char smx[];
    const uint32_t sb = smem_u32(smx);
    const int t = threadIdx.x, lane = t & 31, wid = t >> 5;
    const int wm = wid >> 2, wn = wid & 3;         // 4x4 warp grid, 32x32 each
    const int m0 = blockIdx.y << 7, n0 = blockIdx.x << 7;
    const int mode = qkv ? (int)blockIdx.z : 3;
    const __nv_bfloat16* Ah = (mode == 3) ? g_Chi : g_Xhi;
    const __nv_bfloat16* Al = (mode == 3) ? g_Clo : g_Xlo;
    const __nv_bfloat16* Bh = g_Whi[mode];
    const __nv_bfloat16* Bl = g_Wlo[mode];

    auto issue = [&](int kc) {
        const int kb = kc << 6;
        const uint32_t stb = sb + (uint32_t)(kc % 3) * 65536;
        #pragma unroll
        for (int i = 0; i < 2; i++) {
            int idx = t + (i << 9);
            int row = idx >> 3, ge = (idx & 7) << 3;
            uint32_t so = swz(row * 128 + (ge << 1));
            size_t goa = (size_t)(m0 + row) * 1024 + kb + ge;
            size_t gob = (size_t)(n0 + row) * 1024 + kb + ge;
            cpa16(stb + so,         Ah + goa);
            cpa16(stb + 16384 + so, Al + goa);
            cpa16(stb + 32768 + so, Bh + gob);
            cpa16(stb + 49152 + so, Bl + gob);
        }
        CP_COMMIT();
    };

    const uint32_t a_row = (lane & 7) + ((lane >> 3) & 1) * 8;
    const uint32_t a_kb  = (lane >> 4) * 16;
    const uint32_t b_row = (lane & 7) + (lane >> 4) * 8;
    const uint32_t b_kb  = ((lane >> 3) & 1) * 16;

    float acc[2][4][4] = {};
    issue(0); issue(1);
    for (int kc = 0; kc < 16; kc++) {
        if (kc == 15) { CP_WAIT0(); } else { CP_WAIT1(); }
        __syncthreads();
        const uint32_t stb = sb + (uint32_t)(kc % 3) * 65536;
        #pragma unroll
        for (int ki = 0; ki < 4; ki++) {
            uint32_t ahf[2][4], alf[2][4], bhf[2][4], blf[2][4];
            #pragma unroll
            for (int mi = 0; mi < 2; mi++) {
                uint32_t off = swz(((wm << 5) + (mi << 4) + a_row) * 128 + (ki << 5) + a_kb);
                ldsm4(ahf[mi], stb + off);
                ldsm4(alf[mi], stb + 16384 + off);
            }
            #pragma unroll
            for (int nh = 0; nh < 2; nh++) {
                uint32_t off = swz(((wn << 5) + (nh << 4) + b_row) * 128 + (ki << 5) + b_kb);
                ldsm4(bhf[nh], stb + 32768 + off);
                ldsm4(blf[nh], stb + 49152 + off);
            }
            #pragma unroll
            for (int mi = 0; mi < 2; mi++)
                #pragma unroll
                for (int ni = 0; ni < 4; ni++) {
                    const uint32_t* bh2 = &bhf[ni >> 1][(ni & 1) << 1];
                    const uint32_t* bl2 = &blf[ni >> 1][(ni & 1) << 1];
                    mma16816(acc[mi][ni], ahf[mi], bh2);
                    mma16816(acc[mi][ni], alf[mi], bh2);
                    mma16816(acc[mi][ni], ahf[mi], bl2);
                }
        }
        if (kc + 2 < 16) issue(kc + 2);
    }

    const int g = lane >> 2, tq = lane & 3;
    #pragma unroll
    for (int mi = 0; mi < 2; mi++) {
        #pragma unroll
        for (int ni = 0; ni < 4; ni++) {
            #pragma unroll
            for (int half = 0; half < 2; half++) {
                int r = (wm << 5) + (mi << 4) + g + half * 8;
                int c = (wn << 5) + (ni << 3) + (tq << 1);
                float v0 = acc[mi][ni][half * 2], v1 = acc[mi][ni][half * 2 + 1];
                int m = m0 + r, n = n0 + c;
                if (mode == 3) {
                    *(float2*)&outp[(size_t)m * 1024 + n] = make_float2(v0, v1);
                } else {
                    int b = m >> 11, s = m & 2047, hd = n >> 6, dk = n & 63;
                    size_t o = (((size_t)(b * 16 + hd) * 2048) + s) * 64 + dk;
                    uint32_t hv = h2(v0, v1);
                    if (mode == 2) {
                        *(uint32_t*)(g_V16 + o) = hv;
                    } else {
                        uint32_t lo, hi = pk2(v0, v1, lo);
                        __nv_bfloat16* dh = (mode == 0) ? g_Qhi : g_Khi;
                        __nv_bfloat16* dl = (mode == 0) ? g_Qlo : g_Klo;
                        __half*        df = (mode == 0) ? g_Qf16 : g_Kf16;
                        *(uint32_t*)(dh + o) = hi;
                        *(uint32_t*)(dl + o) = lo;
                        *(uint32_t*)(df + o) = hv;
                    }
                }
            }
        }
    }
}

// ---------------- fused attention: 64q-tile, two-pass softmax + PV, 512 thr ----
// pass 1: 1-term fp16 S rowsums.  pass 2: 3-term bf16 S (stored), 1-term fp16 PV.
// smem: QH 0 (8K), QL 8192, QF 16384 (8K), rowsm 24576 (64f), rinv 24832 (64f),
//       bias s @ 25600+s*1024 (191f), mask s @ 27648+s*512 (128i),
//       stages @ 28672 + s*49152: pass1 {KF +0 16K}  pass2 {KH +0, KL +16K, V16 +32K}
//       PV-reduce buffer reuses 28672.. (64KB) after last tile.
__global__ __launch_bounds__(512) void attn_fused(const int* __restrict__ mask,
                                                  float* __restrict__ attn) {
    extern __shared__ __align__(1024) char smx[];
    const uint32_t sb = smem_u32(smx);
    float* rowsm = (float*)(smx + 24576);
    float* rinv  = (float*)(smx + 24832);
    const int t = threadIdx.x, lane = t & 31, wid = t >> 5;
    const int wm = wid >> 2, wn = wid & 3;          // wm: q 16-row slice, wn: k 32-slice
    const int q0 = blockIdx.x << 6, bh = blockIdx.y, b = bh >> 4, h = bh & 15;
    const int g = lane >> 2, tq = lane & 3;

    // persistent Q tiles: bf16 hi/lo + fp16
    {
        int row = t >> 3, ge = (t & 7) << 3;
        uint32_t so = swz(row * 128 + (ge << 1));
        size_t go = ((size_t)bh * 2048 + q0 + row) * 64 + ge;
        *(uint4*)(smx + so)         = *(const uint4*)(g_Qhi + go);
        *(uint4*)(smx + 8192 + so)  = *(const uint4*)(g_Qlo + go);
        *(uint4*)(smx + 16384 + so) = *(const uint4*)(g_Qf16 + go);
    }
    if (t < 64) rowsm[t] = 0.f;
    __syncthreads();

    const uint32_t a_row = (lane & 7) + ((lane >> 3) & 1) * 8;
    const uint32_t a_kb  = (lane >> 4) * 16;
    const uint32_t b_row = (lane & 7) + (lane >> 4) * 8;
    const uint32_t b_kb  = ((lane >> 3) & 1) * 16;

    // lvl: 0 = KF fp16 only (pass 1), 1 = KH+KL+V16 (pass 2)
    auto issue = [&](int kt, int lvl) {
        const int k0 = kt << 7, s = kt & 1;
        const uint32_t stb = sb + 28672 + (uint32_t)s * 49152;
        #pragma unroll
        for (int i = 0; i < 2; i++) {
            int idx = t + (i << 9);
            int row = idx >> 3, ge = (idx & 7) << 3;
            uint32_t so = swz(row * 128 + (ge << 1));
            size_t go = ((size_t)bh * 2048 + k0 + row) * 64 + ge;
            if (lvl) {
                cpa16(stb + so,         g_Khi + go);
                cpa16(stb + 16384 + so, g_Klo + go);
                cpa16(stb + 32768 + so, g_V16 + go);
            } else {
                cpa16(stb + so, g_Kf16 + go);
            }
        }
        CP_COMMIT();
        float* bw = (float*)(smx + 25600 + s * 1024);
        int*   ms = (int*)(smx + 27648 + s * 512);
        if (t < 191) bw[t] = g_bias[h * 4096 + (k0 - q0 + 1985) + t];
        if (t < 128) ms[t] = mask[b * 2048 + k0 + t];
    };

    // ---------------- pass 1: row sums (1-term fp16 S) ----------------
    {
        uint32_t qf[4][4];
        #pragma unroll
        for (int ki = 0; ki < 4; ki++) {
            uint32_t off = swz(((wm << 4) + a_row) * 128 + (ki << 5) + a_kb);
            ldsm4(qf[ki], sb + 16384 + off);
        }
        float rowpart[2] = {};
        issue(0, 0);
        for (int kt = 0; kt < 16; kt++) {
            if (kt + 1 < 16) { issue(kt + 1, 0); CP_WAIT1(); }
            else             { CP_WAIT0(); }
            __syncthreads();
            const uint32_t kbb = sb + 28672 + (uint32_t)(kt & 1) * 49152;
            float acc[4][4] = {};
            #pragma unroll
            for (int ki = 0; ki < 4; ki++) {
                uint32_t bhf[2][4];
                #pragma unroll
                for (int nh = 0; nh < 2; nh++) {
                    uint32_t off = swz(((wn << 5) + (nh << 4) + b_row) * 128 + (ki << 5) + b_kb);
                    ldsm4(bhf[nh], kbb + off);
                }
                #pragma unroll
                for (int ni = 0; ni < 4; ni++)
                    mma16816h(acc[ni], qf[ki], &bhf[ni >> 1][(ni & 1) << 1]);
            }
            const float* bw = (const float*)(smx + 25600 + (kt & 1) * 1024);
            const int*   ms = (const int*)(smx + 27648 + (kt & 1) * 512);
            #pragma unroll
            for (int half = 0; half < 2; half++) {
                int r = (wm << 4) + g + half * 8;
                float rp = 0.f;
                #pragma unroll
                for (int ni = 0; ni < 4; ni++) {
                    int c = (wn << 5) + (ni << 3) + (tq << 1);
                    float s0 = fmaf(acc[ni][half * 2],     0.125f, bw[c - r + 63]);
                    float s1 = fmaf(acc[ni][half * 2 + 1], 0.125f, bw[c + 1 - r + 63]);
                    rp += (ms[c]     ? __expf(s0) : 0.f);
                    rp += (ms[c + 1] ? __expf(s1) : 0.f);
                }
                rowpart[half] += rp;
            }
            __syncthreads();
        }
        #pragma unroll
        for (int half = 0; half < 2; half++) {
            float v = rowpart[half];
            v += __shfl_xor_sync(0xffffffffu, v, 1);
            v += __shfl_xor_sync(0xffffffffu, v, 2);
            if (tq == 0)
                atomicAdd(&rowsm[(wm << 4) + g + half * 8], v);
        }
    }
    __syncthreads();
    if (t < 64) rinv[t] = 1.0f / rowsm[t];
    __syncthreads();
    float riv[2];
    #pragma unroll
    for (int half = 0; half < 2; half++)
        riv[half] = rinv[(wm << 4) + g + half * 8];

    // ---------------- pass 2: normalized attn store + fp16 PV ----------------
    uint32_t qh1[4][4], ql1[4][4];
    #pragma unroll
    for (int ki = 0; ki < 4; ki++) {
        uint32_t off = swz(((wm << 4) + a_row) * 128 + (ki << 5) + a_kb);
        ldsm4(qh1[ki], sb + off);
        ldsm4(ql1[ki], sb + 8192 + off);
    }
    float pv[8][4] = {};
    issue(0, 1);
    for (int kt = 0; kt < 16; kt++) {
        const int k0 = kt << 7;
        if (kt + 1 < 16) { issue(kt + 1, 1); CP_WAIT1(); }
        else             { CP_WAIT0(); }
        __syncthreads();
        const uint32_t kbb = sb + 28672 + (uint32_t)(kt & 1) * 49152;
        float acc[4][4] = {};
        #pragma unroll
        for (int ki = 0; ki < 4; ki++) {
            uint32_t bhf[2][4], blf[2][4];
            #pragma unroll
            for (int nh = 0; nh < 2; nh++) {
                uint32_t off = swz(((wn << 5) + (nh << 4) + b_row) * 128 + (ki << 5) + b_kb);
                ldsm4(bhf[nh], kbb + off);
                ldsm4(blf[nh], kbb + 16384 + off);
            }
            #pragma unroll
            for (int ni = 0; ni < 4; ni++) {
                const uint32_t* bh2 = &bhf[ni >> 1][(ni & 1) << 1];
                const uint32_t* bl2 = &blf[ni >> 1][(ni & 1) << 1];
                mma16816(acc[ni], qh1[ki], bh2);
                mma16816(acc[ni], ql1[ki], bh2);
                mma16816(acc[ni], qh1[ki], bl2);
            }
        }
        const float* bw = (const float*)(smx + 25600 + (kt & 1) * 1024);
        const int*   ms = (const int*)(smx + 27648 + (kt & 1) * 512);
        #pragma unroll
        for (int half = 0; half < 2; half++) {
            int r = (wm << 4) + g + half * 8;
            float ri = riv[half];
            #pragma unroll
            for (int ni = 0; ni < 4; ni++) {
                int c = (wn << 5) + (ni << 3) + (tq << 1);
                float s0 = fmaf(acc[ni][half * 2],     0.125f, bw[c - r + 63]);
                float s1 = fmaf(acc[ni][half * 2 + 1], 0.125f, bw[c + 1 - r + 63]);
                float e0 = (ms[c]     ? __expf(s0) : 0.f) * ri;
                float e1 = (ms[c + 1] ? __expf(s1) : 0.f) * ri;
                *(float2*)&attn[((size_t)bh * 2048 + q0 + r) * 2048 + k0 + c] =
                    make_float2(e0, e1);
                acc[ni][half * 2]     = e0;
                acc[ni][half * 2 + 1] = e1;
            }
        }
        // PV: P (fp16) x V (fp16), single term
        const uint32_t vbase = sb + 28672 + (uint32_t)(kt & 1) * 49152 + 32768;
        #pragma unroll
        for (int j = 0; j < 2; j++) {
            uint32_t Ahh[4];
            Ahh[0] = h2(acc[2*j][0],   acc[2*j][1]);
            Ahh[1] = h2(acc[2*j][2],   acc[2*j][3]);
            Ahh[2] = h2(acc[2*j+1][0], acc[2*j+1][1]);
            Ahh[3] = h2(acc[2*j+1][2], acc[2*j+1][3]);
            #pragma unroll
            for (int dvg = 0; dvg < 4; dvg++) {
                uint32_t vf[4];
                uint32_t off = swz(((wn << 5) + (j << 4) + a_row) * 128 + (dvg << 5) + a_kb);
                ldsm4t(vf, vbase + off);
                #pragma unroll
                for (int n8 = 0; n8 < 2; n8++)
                    mma16816h(pv[dvg * 2 + n8], Ahh, &vf[n8 << 1]);
            }
        }
        __syncthreads();
    }

    // ---------------- cross-warp PV reduction + ctx store ----------------
    #pragma unroll
    for (int ni = 0; ni < 8; ni++)
        #pragma unroll
        for (int half = 0; half < 2; half++) {
            int row = (wm << 4) + g + half * 8;
            uint32_t off = 28672 + (uint32_t)wn * 16384 + row * 256 + ((ni << 3) + (tq << 1)) * 4;
            *(float2*)(smx + off) = make_float2(pv[ni][half * 2], pv[ni][half * 2 + 1]);
        }
    __syncthreads();
    #pragma unroll
    for (int i = 0; i < 4; i++) {
        int idx = t + (i << 9);
        int row = idx >> 5, dvp = idx & 31;
        float sx = 0.f, sy = 0.f;
        #pragma unroll
        for (int w = 0; w < 4; w++) {
            float2 v = *(float2*)(smx + 28672 + w * 16384 + row * 256 + dvp * 8);
            sx += v.x; sy += v.y;
        }
        uint32_t lo, hi = pk2(sx, sy, lo);
        size_t o = ((size_t)(b * 2048 + q0 + row)) * 1024 + (h << 6) + dvp * 2;
        *(uint32_t*)(g_Chi + o) = hi;
        *(uint32_t*)(g_Clo + o) = lo;
    }
}

// ---------------- launch --------------------------------------------------------
#define PROJ_SMEM 196608
#define ATT_SMEM  126976

extern "C" void kernel_launch(void* const* d_in, const int* in_sizes, int n_in,
                              void* d_out, int out_size) {
    const float* hs   = (const float*)d_in[0];
    const int*   mask = (const int*)d_in[1];
    const float* Wq   = (const float*)d_in[2];
    const float* Wk   = (const float*)d_in[3];
    const float* Wv   = (const float*)d_in[4];
    const float* Wo   = (const float*)d_in[5];
    const float* rb   = (const float*)d_in[6];
    float* out  = (float*)d_out;
    float* attn = out + 4194304;

    cudaFuncSetAttribute(proj_gemm,  cudaFuncAttributeMaxDynamicSharedMemorySize, PROJ_SMEM);
    cudaFuncSetAttribute(attn_fused, cudaFuncAttributeMaxDynamicSharedMemorySize, ATT_SMEM);

    bias_init<<<16, 256>>>(rb);
    split_x<<<4096, 256>>>(hs);
    wsplit<<<dim3(32, 32, 4), dim3(32, 8)>>>(Wq, Wk, Wv, Wo);

    proj_gemm<<<dim3(8, 32, 3), 512, PROJ_SMEM>>>(nullptr, 1);   // Q,K,V fused

    attn_fused<<<dim3(32, 32), 512, ATT_SMEM>>>(mask, attn);     // softmax+attn+ctx

    proj_gemm<<<dim3(8, 32, 1), 512, PROJ_SMEM>>>(out, 0);       // ctx @ Wo
}

// round 14
// speedup vs baseline: 1.3785x; 1.2063x over previous
#include <cuda_runtime.h>
#include <cuda_fp16.h>
#include <cstdint>

// ---------------- scratch (static device arrays; no cudaMalloc) -------------
__device__ __align__(16) __half g_Xh[4194304], g_Xl[4194304];
__device__ __align__(16) __half g_Wh[4][1048576];                // [n][k] fp16
__device__ __align__(16) __half g_Qh[4194304], g_Ql[4194304];    // [bh][s][64]
__device__ __align__(16) __half g_K16[4194304], g_V16[4194304];  // [bh][s][64]
__device__ __align__(16) __half g_Ch[4194304], g_Cl[4194304];    // [m][1024]
__device__ float g_bias[16 * 4096];

// ---------------- helpers -----------------------------------------------------
__device__ __forceinline__ uint32_t smem_u32(const void* p) {
    uint32_t a;
    asm("{ .reg .u64 t; cvta.to.shared.u64 t, %1; cvt.u32.u64 %0, t; }" : "=r"(a) : "l"(p));
    return a;
}
__device__ __forceinline__ uint32_t swz(uint32_t off) { return off ^ ((off >> 3) & 0x70); }

__device__ __forceinline__ void cpa16(uint32_t saddr, const void* g) {
    asm volatile("cp.async.cg.shared.global [%0], [%1], 16;" :: "r"(saddr), "l"(g));
}
#define CP_COMMIT() asm volatile("cp.async.commit_group;" ::: "memory")
#define CP_WAIT1()  asm volatile("cp.async.wait_group 1;" ::: "memory")
#define CP_WAIT0()  asm volatile("cp.async.wait_group 0;" ::: "memory")

__device__ __forceinline__ void ldsm4(uint32_t* r, uint32_t addr) {
    asm volatile("ldmatrix.sync.aligned.m8n8.x4.shared.b16 {%0,%1,%2,%3}, [%4];"
        : "=r"(r[0]), "=r"(r[1]), "=r"(r[2]), "=r"(r[3]) : "r"(addr));
}
__device__ __forceinline__ void ldsm4t(uint32_t* r, uint32_t addr) {
    asm volatile("ldmatrix.sync.aligned.m8n8.x4.trans.shared.b16 {%0,%1,%2,%3}, [%4];"
        : "=r"(r[0]), "=r"(r[1]), "=r"(r[2]), "=r"(r[3]) : "r"(addr));
}
__device__ __forceinline__ void mma16816h(float* d, const uint32_t* a, const uint32_t* b) {
    asm volatile("mma.sync.aligned.m16n8k16.row.col.f32.f16.f16.f32 "
        "{%0,%1,%2,%3}, {%4,%5,%6,%7}, {%8,%9}, {%0,%1,%2,%3};"
        : "+f"(d[0]), "+f"(d[1]), "+f"(d[2]), "+f"(d[3])
        : "r"(a[0]), "r"(a[1]), "r"(a[2]), "r"(a[3]), "r"(b[0]), "r"(b[1]));
}
__device__ __forceinline__ uint32_t h2(float a, float b) {
    __half2 h = __floats2half2_rn(a, b);
    return *(uint32_t*)&h;
}
// fp16 hi/lo split of 2 floats
__device__ __forceinline__ uint32_t pkh2(float a, float b, uint32_t& lo) {
    __half2 h = __floats2half2_rn(a, b);
    __half2 l = __floats2half2_rn(a - __half2float(__low2half(h)),
                                  b - __half2float(__high2half(h)));
    lo = *(uint32_t*)&l;
    return *(uint32_t*)&h;
}

// ---------------- prep kernels -------------------------------------------------
__global__ void bias_init(const float* __restrict__ rel_bias) {
    int d = blockIdx.x * 256 + threadIdx.x;
    if (d >= 4096) return;
    int n = -(d - 2048);
    int ret = 0;
    if (n < 0) { ret = 16; n = -n; }
    int bucket;
    if      (n <  8) bucket = n;
    else if (n < 12) bucket = 8;
    else if (n < 16) bucket = 9;
    else if (n < 23) bucket = 10;
    else if (n < 32) bucket = 11;
    else if (n < 46) bucket = 12;
    else if (n < 64) bucket = 13;
    else if (n < 91) bucket = 14;
    else             bucket = 15;
    bucket += ret;
    #pragma unroll
    for (int h = 0; h < 16; h++)
        g_bias[h * 4096 + d] = rel_bias[bucket * 16 + h];
}

__global__ void split_x(const float* __restrict__ src) {
    size_t i = ((size_t)blockIdx.x * 256 + threadIdx.x) * 4;
    float4 v = *(const float4*)(src + i);
    float x[4] = {v.x, v.y, v.z, v.w};
    #pragma unroll
    for (int j = 0; j < 4; j++) {
        __half hh = __float2half_rn(x[j]);
        g_Xh[i + j] = hh;
        g_Xl[i + j] = __float2half_rn(x[j] - __half2float(hh));
    }
}

__global__ void wsplit(const float* __restrict__ W0, const float* __restrict__ W1,
                       const float* __restrict__ W2, const float* __restrict__ W3) {
    __shared__ float tile[32][33];
    const float* W = blockIdx.z == 0 ? W0 : blockIdx.z == 1 ? W1 : blockIdx.z == 2 ? W2 : W3;
    int n0 = blockIdx.x * 32, k0 = blockIdx.y * 32;
    int tx = threadIdx.x, ty = threadIdx.y;
    #pragma unroll
    for (int j = 0; j < 4; j++)
        tile[ty + j * 8][tx] = W[(size_t)(k0 + ty + j * 8) * 1024 + n0 + tx];
    __syncthreads();
    #pragma unroll
    for (int j = 0; j < 4; j++) {
        float x = tile[tx][ty + j * 8];
        size_t o = (size_t)(n0 + ty + j * 8) * 1024 + k0 + tx;     // [n][k]
        g_Wh[blockIdx.z][o] = __float2half_rn(x);
    }
}

// ---------------- unified 128x128 fp16 2-term GEMM, 3-stage pipeline, 512 thr --
// acc = (Ah + Al) . Bh     (dropped A.Bl term ~1.4e-4 random)
__global__ __launch_bounds__(512) void proj_gemm(float* __restrict__ outp, int qkv) {
    extern __shared__ __align__(1024) char smx[];
    const uint32_t sb = smem_u32(smx);
    const int t = threadIdx.x, lane = t & 31, wid = t >> 5;
    const int wm = wid >> 2, wn = wid & 3;         // 4x4 warp grid, 32x32 each
    const int m0 = blockIdx.y << 7, n0 = blockIdx.x << 7;
    const int mode = qkv ? (int)blockIdx.z : 3;
    const __half* Ah = (mode == 3) ? g_Ch : g_Xh;
    const __half* Al = (mode == 3) ? g_Cl : g_Xl;
    const __half* Bh = g_Wh[mode];

    auto issue = [&](int kc) {
        const int kb = kc << 6;
        const uint32_t stb = sb + (uint32_t)(kc % 3) * 49152;
        #pragma unroll
        for (int i = 0; i < 2; i++) {
            int idx = t + (i << 9);
            int row = idx >> 3, ge = (idx & 7) << 3;
            uint32_t so = swz(row * 128 + (ge << 1));
            size_t goa = (size_t)(m0 + row) * 1024 + kb + ge;
            size_t gob = (size_t)(n0 + row) * 1024 + kb + ge;
            cpa16(stb + so,         Ah + goa);
            cpa16(stb + 16384 + so, Al + goa);
            cpa16(stb + 32768 + so, Bh + gob);
        }
        CP_COMMIT();
    };

    const uint32_t a_row = (lane & 7) + ((lane >> 3) & 1) * 8;
    const uint32_t a_kb  = (lane >> 4) * 16;
    const uint32_t b_row = (lane & 7) + (lane >> 4) * 8;
    const uint32_t b_kb  = ((lane >> 3) & 1) * 16;

    float acc[2][4][4] = {};
    issue(0); issue(1);
    for (int kc = 0; kc < 16; kc++) {
        if (kc == 15) { CP_WAIT0(); } else { CP_WAIT1(); }
        __syncthreads();
        const uint32_t stb = sb + (uint32_t)(kc % 3) * 49152;
        #pragma unroll
        for (int ki = 0; ki < 4; ki++) {
            uint32_t ahf[2][4], alf[2][4], bhf[2][4];
            #pragma unroll
            for (int mi = 0; mi < 2; mi++) {
                uint32_t off = swz(((wm << 5) + (mi << 4) + a_row) * 128 + (ki << 5) + a_kb);
                ldsm4(ahf[mi], stb + off);
                ldsm4(alf[mi], stb + 16384 + off);
            }
            #pragma unroll
            for (int nh = 0; nh < 2; nh++) {
                uint32_t off = swz(((wn << 5) + (nh << 4) + b_row) * 128 + (ki << 5) + b_kb);
                ldsm4(bhf[nh], stb + 32768 + off);
            }
            #pragma unroll
            for (int mi = 0; mi < 2; mi++)
                #pragma unroll
                for (int ni = 0; ni < 4; ni++)
                    mma16816h(acc[mi][ni], ahf[mi], &bhf[ni >> 1][(ni & 1) << 1]);
            #pragma unroll
            for (int mi = 0; mi < 2; mi++)
                #pragma unroll
                for (int ni = 0; ni < 4; ni++)
                    mma16816h(acc[mi][ni], alf[mi], &bhf[ni >> 1][(ni & 1) << 1]);
        }
        if (kc + 2 < 16) issue(kc + 2);
    }

    const int g = lane >> 2, tq = lane & 3;
    #pragma unroll
    for (int mi = 0; mi < 2; mi++) {
        #pragma unroll
        for (int ni = 0; ni < 4; ni++) {
            #pragma unroll
            for (int half = 0; half < 2; half++) {
                int r = (wm << 5) + (mi << 4) + g + half * 8;
                int c = (wn << 5) + (ni << 3) + (tq << 1);
                float v0 = acc[mi][ni][half * 2], v1 = acc[mi][ni][half * 2 + 1];
                int m = m0 + r, n = n0 + c;
                if (mode == 3) {
                    *(float2*)&outp[(size_t)m * 1024 + n] = make_float2(v0, v1);
                } else {
                    int b = m >> 11, s = m & 2047, hd = n >> 6, dk = n & 63;
                    size_t o = (((size_t)(b * 16 + hd) * 2048) + s) * 64 + dk;
                    if (mode == 0) {               // Q: fp16 hi/lo
                        uint32_t lo, hi = pkh2(v0, v1, lo);
                        *(uint32_t*)(g_Qh + o) = hi;
                        *(uint32_t*)(g_Ql + o) = lo;
                    } else {                       // K / V: single fp16
                        uint32_t hv = h2(v0, v1);
                        __half* d = (mode == 1) ? g_K16 : g_V16;
                        *(uint32_t*)(d + o) = hv;
                    }
                }
            }
        }
    }
}

// ---------------- fused attention: 64q-tile, two-pass softmax + PV, 512 thr ----
// pass 1: 1-term fp16 S rowsums.  pass 2: 2-term fp16 S (stored), 1-term fp16 PV.
// smem: QH 0 (8K), QL 8192 (8K), rowsm 16384 (64f), rinv 16640 (64f),
//       bias s @ 17408+s*1024 (191f), mask s @ 19456+s*512 (128i),
//       stages @ 20480 + s*32768: {K16 +0 (16K), V16 +16384 (16K)}
//       PV-reduce buffer reuses 20480.. (64KB) after last tile.
__global__ __launch_bounds__(512) void attn_fused(const int* __restrict__ mask,
                                                  float* __restrict__ attn) {
    extern __shared__ __align__(1024) char smx[];
    const uint32_t sb = smem_u32(smx);
    float* rowsm = (float*)(smx + 16384);
    float* rinv  = (float*)(smx + 16640);
    const int t = threadIdx.x, lane = t & 31, wid = t >> 5;
    const int wm = wid >> 2, wn = wid & 3;          // wm: q 16-row slice, wn: k 32-slice
    const int q0 = blockIdx.x << 6, bh = blockIdx.y, b = bh >> 4, h = bh & 15;
    const int g = lane >> 2, tq = lane & 3;

    // persistent Q tiles: fp16 hi/lo
    {
        int row = t >> 3, ge = (t & 7) << 3;
        uint32_t so = swz(row * 128 + (ge << 1));
        size_t go = ((size_t)bh * 2048 + q0 + row) * 64 + ge;
        *(uint4*)(smx + so)        = *(const uint4*)(g_Qh + go);
        *(uint4*)(smx + 8192 + so) = *(const uint4*)(g_Ql + go);
    }
    if (t < 64) rowsm[t] = 0.f;
    __syncthreads();

    const uint32_t a_row = (lane & 7) + ((lane >> 3) & 1) * 8;
    const uint32_t a_kb  = (lane >> 4) * 16;
    const uint32_t b_row = (lane & 7) + (lane >> 4) * 8;
    const uint32_t b_kb  = ((lane >> 3) & 1) * 16;

    // lvl: 0 = K16 only (pass 1), 1 = K16+V16 (pass 2)
    auto issue = [&](int kt, int lvl) {
        const int k0 = kt << 7, s = kt & 1;
        const uint32_t stb = sb + 20480 + (uint32_t)s * 32768;
        #pragma unroll
        for (int i = 0; i < 2; i++) {
            int idx = t + (i << 9);
            int row = idx >> 3, ge = (idx & 7) << 3;
            uint32_t so = swz(row * 128 + (ge << 1));
            size_t go = ((size_t)bh * 2048 + k0 + row) * 64 + ge;
            cpa16(stb + so, g_K16 + go);
            if (lvl) cpa16(stb + 16384 + so, g_V16 + go);
        }
        CP_COMMIT();
        float* bw = (float*)(smx + 17408 + s * 1024);
        int*   ms = (int*)(smx + 19456 + s * 512);
        if (t < 191) bw[t] = g_bias[h * 4096 + (k0 - q0 + 1985) + t];
        if (t < 128) ms[t] = mask[b * 2048 + k0 + t];
    };

    // hoist this warp's Q fragments (16 q-rows, k-invariant), hi + lo
    uint32_t qh1[4][4], ql1[4][4];
    #pragma unroll
    for (int ki = 0; ki < 4; ki++) {
        uint32_t off = swz(((wm << 4) + a_row) * 128 + (ki << 5) + a_kb);
        ldsm4(qh1[ki], sb + off);
        ldsm4(ql1[ki], sb + 8192 + off);
    }

    // ---------------- pass 1: row sums (1-term fp16 S) ----------------
    {
        float rowpart[2] = {};
        issue(0, 0);
        for (int kt = 0; kt < 16; kt++) {
            if (kt + 1 < 16) { issue(kt + 1, 0); CP_WAIT1(); }
            else             { CP_WAIT0(); }
            __syncthreads();
            const uint32_t kbb = sb + 20480 + (uint32_t)(kt & 1) * 32768;
            float acc[4][4] = {};
            #pragma unroll
            for (int ki = 0; ki < 4; ki++) {
                uint32_t bhf[2][4];
                #pragma unroll
                for (int nh = 0; nh < 2; nh++) {
                    uint32_t off = swz(((wn << 5) + (nh << 4) + b_row) * 128 + (ki << 5) + b_kb);
                    ldsm4(bhf[nh], kbb + off);
                }
                #pragma unroll
                for (int ni = 0; ni < 4; ni++)
                    mma16816h(acc[ni], qh1[ki], &bhf[ni >> 1][(ni & 1) << 1]);
            }
            const float* bw = (const float*)(smx + 17408 + (kt & 1) * 1024);
            const int*   ms = (const int*)(smx + 19456 + (kt & 1) * 512);
            #pragma unroll
            for (int half = 0; half < 2; half++) {
                int r = (wm << 4) + g + half * 8;
                float rp = 0.f;
                #pragma unroll
                for (int ni = 0; ni < 4; ni++) {
                    int c = (wn << 5) + (ni << 3) + (tq << 1);
                    float s0 = fmaf(acc[ni][half * 2],     0.125f, bw[c - r + 63]);
                    float s1 = fmaf(acc[ni][half * 2 + 1], 0.125f, bw[c + 1 - r + 63]);
                    rp += (ms[c]     ? __expf(s0) : 0.f);
                    rp += (ms[c + 1] ? __expf(s1) : 0.f);
                }
                rowpart[half] += rp;
            }
            __syncthreads();
        }
        #pragma unroll
        for (int half = 0; half < 2; half++) {
            float v = rowpart[half];
            v += __shfl_xor_sync(0xffffffffu, v, 1);
            v += __shfl_xor_sync(0xffffffffu, v, 2);
            if (tq == 0)
                atomicAdd(&rowsm[(wm << 4) + g + half * 8], v);
        }
    }
    __syncthreads();
    if (t < 64) rinv[t] = 1.0f / rowsm[t];
    __syncthreads();
    float riv[2];
    #pragma unroll
    for (int half = 0; half < 2; half++)
        riv[half] = rinv[(wm << 4) + g + half * 8];

    // ---------------- pass 2: normalized attn store (2-term S) + fp16 PV -------
    float pv[8][4] = {};
    issue(0, 1);
    for (int kt = 0; kt < 16; kt++) {
        const int k0 = kt << 7;
        if (kt + 1 < 16) { issue(kt + 1, 1); CP_WAIT1(); }
        else             { CP_WAIT0(); }
        __syncthreads();
        const uint32_t kbb = sb + 20480 + (uint32_t)(kt & 1) * 32768;
        float acc[4][4] = {};
        #pragma unroll
        for (int ki = 0; ki < 4; ki++) {
            uint32_t bhf[2][4];
            #pragma unroll
            for (int nh = 0; nh < 2; nh++) {
                uint32_t off = swz(((wn << 5) + (nh << 4) + b_row) * 128 + (ki << 5) + b_kb);
                ldsm4(bhf[nh], kbb + off);
            }
            #pragma unroll
            for (int ni = 0; ni < 4; ni++)
                mma16816h(acc[ni], qh1[ki], &bhf[ni >> 1][(ni & 1) << 1]);
            #pragma unroll
            for (int ni = 0; ni < 4; ni++)
                mma16816h(acc[ni], ql1[ki], &bhf[ni >> 1][(ni & 1) << 1]);
        }
        const float* bw = (const float*)(smx + 17408 + (kt & 1) * 1024);
        const int*   ms = (const int*)(smx + 19456 + (kt & 1) * 512);
        #pragma unroll
        for (int half = 0; half < 2; half++) {
            int r = (wm << 4) + g + half * 8;
            float ri = riv[half];
            #pragma unroll
            for (int ni = 0; ni < 4; ni++) {
                int c = (wn << 5) + (ni << 3) + (tq << 1);
                float s0 = fmaf(acc[ni][half * 2],     0.125f, bw[c - r + 63]);
                float s1 = fmaf(acc[ni][half * 2 + 1], 0.125f, bw[c + 1 - r + 63]);
                float e0 = (ms[c]     ? __expf(s0) : 0.f) * ri;
                float e1 = (ms[c + 1] ? __expf(s1) : 0.f) * ri;
                *(float2*)&attn[((size_t)bh * 2048 + q0 + r) * 2048 + k0 + c] =
                    make_float2(e0, e1);
                acc[ni][half * 2]     = e0;
                acc[ni][half * 2 + 1] = e1;
            }
        }
        // PV: P (fp16) x V (fp16), single term
        const uint32_t vbase = sb + 20480 + (uint32_t)(kt & 1) * 32768 + 16384;
        #pragma unroll
        for (int j = 0; j < 2; j++) {
            uint32_t Ahh[4];
            Ahh[0] = h2(acc[2*j][0],   acc[2*j][1]);
            Ahh[1] = h2(acc[2*j][2],   acc[2*j][3]);
            Ahh[2] = h2(acc[2*j+1][0], acc[2*j+1][1]);
            Ahh[3] = h2(acc[2*j+1][2], acc[2*j+1][3]);
            #pragma unroll
            for (int dvg = 0; dvg < 4; dvg++) {
                uint32_t vf[4];
                uint32_t off = swz(((wn << 5) + (j << 4) + a_row) * 128 + (dvg << 5) + a_kb);
                ldsm4t(vf, vbase + off);
                #pragma unroll
                for (int n8 = 0; n8 < 2; n8++)
                    mma16816h(pv[dvg * 2 + n8], Ahh, &vf[n8 << 1]);
            }
        }
        __syncthreads();
    }

    // ---------------- cross-warp PV reduction + ctx store (fp16 hi/lo) ---------
    #pragma unroll
    for (int ni = 0; ni < 8; ni++)
        #pragma unroll
        for (int half = 0; half < 2; half++) {
            int row = (wm << 4) + g + half * 8;
            uint32_t off = 20480 + (uint32_t)wn * 16384 + row * 256 + ((ni << 3) + (tq << 1)) * 4;
            *(float2*)(smx + off) = make_float2(pv[ni][half * 2], pv[ni][half * 2 + 1]);
        }
    __syncthreads();
    #pragma unroll
    for (int i = 0; i < 4; i++) {
        int idx = t + (i << 9);
        int row = idx >> 5, dvp = idx & 31;
        float sx = 0.f, sy = 0.f;
        #pragma unroll
        for (int w = 0; w < 4; w++) {
            float2 v = *(float2*)(smx + 20480 + w * 16384 + row * 256 + dvp * 8);
            sx += v.x; sy += v.y;
        }
        uint32_t lo, hi = pkh2(sx, sy, lo);
        size_t o = ((size_t)(b * 2048 + q0 + row)) * 1024 + (h << 6) + dvp * 2;
        *(uint32_t*)(g_Ch + o) = hi;
        *(uint32_t*)(g_Cl + o) = lo;
    }
}

// ---------------- launch --------------------------------------------------------
#define PROJ_SMEM 147456
#define ATT_SMEM  86016

extern "C" void kernel_launch(void* const* d_in, const int* in_sizes, int n_in,
                              void* d_out, int out_size) {
    const float* hs   = (const float*)d_in[0];
    const int*   mask = (const int*)d_in[1];
    const float* Wq   = (const float*)d_in[2];
    const float* Wk   = (const float*)d_in[3];
    const float* Wv   = (const float*)d_in[4];
    const float* Wo   = (const float*)d_in[5];
    const float* rb   = (const float*)d_in[6];
    float* out  = (float*)d_out;
    float* attn = out + 4194304;

    cudaFuncSetAttribute(proj_gemm,  cudaFuncAttributeMaxDynamicSharedMemorySize, PROJ_SMEM);
    cudaFuncSetAttribute(attn_fused, cudaFuncAttributeMaxDynamicSharedMemorySize, ATT_SMEM);

    bias_init<<<16, 256>>>(rb);
    split_x<<<4096, 256>>>(hs);
    wsplit<<<dim3(32, 32, 4), dim3(32, 8)>>>(Wq, Wk, Wv, Wo);

    proj_gemm<<<dim3(8, 32, 3), 512, PROJ_SMEM>>>(nullptr, 1);   // Q,K,V fused

    attn_fused<<<dim3(32, 32), 512, ATT_SMEM>>>(mask, attn);     // softmax+attn+ctx

    proj_gemm<<<dim3(8, 32, 1), 512, PROJ_SMEM>>>(out, 0);       // ctx @ Wo
}

// round 15
// speedup vs baseline: 1.4343x; 1.0405x over previous
#include <cuda_runtime.h>
#include <cuda_fp16.h>
#include <cstdint>

// ---------------- scratch (static device arrays; no cudaMalloc) -------------
__device__ __align__(16) __half g_Xh[4194304], g_Xl[4194304];
__device__ __align__(16) __half g_Wh[4][1048576];                // [n][k] fp16
__device__ __align__(16) __half g_Q16[4194304];                  // [bh][s][64]
__device__ __align__(16) __half g_K16[4194304], g_V16[4194304];  // [bh][s][64]
__device__ __align__(16) __half g_Ch[4194304], g_Cl[4194304];    // [m][1024]
__device__ float g_bias[16 * 4096];

// ---------------- helpers -----------------------------------------------------
__device__ __forceinline__ uint32_t smem_u32(const void* p) {
    uint32_t a;
    asm("{ .reg .u64 t; cvta.to.shared.u64 t, %1; cvt.u32.u64 %0, t; }" : "=r"(a) : "l"(p));
    return a;
}
__device__ __forceinline__ uint32_t swz(uint32_t off) { return off ^ ((off >> 3) & 0x70); }

__device__ __forceinline__ void cpa16(uint32_t saddr, const void* g) {
    asm volatile("cp.async.cg.shared.global [%0], [%1], 16;" :: "r"(saddr), "l"(g));
}
#define CP_COMMIT() asm volatile("cp.async.commit_group;" ::: "memory")
#define CP_WAIT1()  asm volatile("cp.async.wait_group 1;" ::: "memory")
#define CP_WAIT0()  asm volatile("cp.async.wait_group 0;" ::: "memory")

__device__ __forceinline__ void ldsm4(uint32_t* r, uint32_t addr) {
    asm volatile("ldmatrix.sync.aligned.m8n8.x4.shared.b16 {%0,%1,%2,%3}, [%4];"
        : "=r"(r[0]), "=r"(r[1]), "=r"(r[2]), "=r"(r[3]) : "r"(addr));
}
__device__ __forceinline__ void ldsm4t(uint32_t* r, uint32_t addr) {
    asm volatile("ldmatrix.sync.aligned.m8n8.x4.trans.shared.b16 {%0,%1,%2,%3}, [%4];"
        : "=r"(r[0]), "=r"(r[1]), "=r"(r[2]), "=r"(r[3]) : "r"(addr));
}
__device__ __forceinline__ void mma16816h(float* d, const uint32_t* a, const uint32_t* b) {
    asm volatile("mma.sync.aligned.m16n8k16.row.col.f32.f16.f16.f32 "
        "{%0,%1,%2,%3}, {%4,%5,%6,%7}, {%8,%9}, {%0,%1,%2,%3};"
        : "+f"(d[0]), "+f"(d[1]), "+f"(d[2]), "+f"(d[3])
        : "r"(a[0]), "r"(a[1]), "r"(a[2]), "r"(a[3]), "r"(b[0]), "r"(b[1]));
}
__device__ __forceinline__ uint32_t h2(float a, float b) {
    __half2 h = __floats2half2_rn(a, b);
    return *(uint32_t*)&h;
}
__device__ __forceinline__ uint32_t pkh2(float a, float b, uint32_t& lo) {
    __half2 h = __floats2half2_rn(a, b);
    __half2 l = __floats2half2_rn(a - __half2float(__low2half(h)),
                                  b - __half2float(__high2half(h)));
    lo = *(uint32_t*)&l;
    return *(uint32_t*)&h;
}

// ---------------- prep kernels -------------------------------------------------
__global__ void bias_init(const float* __restrict__ rel_bias) {
    int d = blockIdx.x * 256 + threadIdx.x;
    if (d >= 4096) return;
    int n = -(d - 2048);
    int ret = 0;
    if (n < 0) { ret = 16; n = -n; }
    int bucket;
    if      (n <  8) bucket = n;
    else if (n < 12) bucket = 8;
    else if (n < 16) bucket = 9;
    else if (n < 23) bucket = 10;
    else if (n < 32) bucket = 11;
    else if (n < 46) bucket = 12;
    else if (n < 64) bucket = 13;
    else if (n < 91) bucket = 14;
    else             bucket = 15;
    bucket += ret;
    #pragma unroll
    for (int h = 0; h < 16; h++)
        g_bias[h * 4096 + d] = rel_bias[bucket * 16 + h];
}

__global__ void split_x(const float* __restrict__ src) {
    size_t i = ((size_t)blockIdx.x * 256 + threadIdx.x) * 4;
    float4 v = *(const float4*)(src + i);
    float x[4] = {v.x, v.y, v.z, v.w};
    #pragma unroll
    for (int j = 0; j < 4; j++) {
        __half hh = __float2half_rn(x[j]);
        g_Xh[i + j] = hh;
        g_Xl[i + j] = __float2half_rn(x[j] - __half2float(hh));
    }
}

__global__ void wsplit(const float* __restrict__ W0, const float* __restrict__ W1,
                       const float* __restrict__ W2, const float* __restrict__ W3) {
    __shared__ float tile[32][33];
    const float* W = blockIdx.z == 0 ? W0 : blockIdx.z == 1 ? W1 : blockIdx.z == 2 ? W2 : W3;
    int n0 = blockIdx.x * 32, k0 = blockIdx.y * 32;
    int tx = threadIdx.x, ty = threadIdx.y;
    #pragma unroll
    for (int j = 0; j < 4; j++)
        tile[ty + j * 8][tx] = W[(size_t)(k0 + ty + j * 8) * 1024 + n0 + tx];
    __syncthreads();
    #pragma unroll
    for (int j = 0; j < 4; j++) {
        float x = tile[tx][ty + j * 8];
        size_t o = (size_t)(n0 + ty + j * 8) * 1024 + k0 + tx;     // [n][k]
        g_Wh[blockIdx.z][o] = __float2half_rn(x);
    }
}

// ---------------- unified 128x128 fp16 2-term GEMM, 3-stage pipeline, 512 thr --
// acc = (Ah + Al) . Bh
__global__ __launch_bounds__(512) void proj_gemm(float* __restrict__ outp, int qkv) {
    extern __shared__ __align__(1024) char smx[];
    const uint32_t sb = smem_u32(smx);
    const int t = threadIdx.x, lane = t & 31, wid = t >> 5;
    const int wm = wid >> 2, wn = wid & 3;         // 4x4 warp grid, 32x32 each
    const int m0 = blockIdx.y << 7, n0 = blockIdx.x << 7;
    const int mode = qkv ? (int)blockIdx.z : 3;
    const __half* Ah = (mode == 3) ? g_Ch : g_Xh;
    const __half* Al = (mode == 3) ? g_Cl : g_Xl;
    const __half* Bh = g_Wh[mode];

    auto issue = [&](int kc) {
        const int kb = kc << 6;
        const uint32_t stb = sb + (uint32_t)(kc % 3) * 49152;
        #pragma unroll
        for (int i = 0; i < 2; i++) {
            int idx = t + (i << 9);
            int row = idx >> 3, ge = (idx & 7) << 3;
            uint32_t so = swz(row * 128 + (ge << 1));
            size_t goa = (size_t)(m0 + row) * 1024 + kb + ge;
            size_t gob = (size_t)(n0 + row) * 1024 + kb + ge;
            cpa16(stb + so,         Ah + goa);
            cpa16(stb + 16384 + so, Al + goa);
            cpa16(stb + 32768 + so, Bh + gob);
        }
        CP_COMMIT();
    };

    const uint32_t a_row = (lane & 7) + ((lane >> 3) & 1) * 8;
    const uint32_t a_kb  = (lane >> 4) * 16;
    const uint32_t b_row = (lane & 7) + (lane >> 4) * 8;
    const uint32_t b_kb  = ((lane >> 3) & 1) * 16;

    float acc[2][4][4] = {};
    issue(0); issue(1);
    for (int kc = 0; kc < 16; kc++) {
        if (kc == 15) { CP_WAIT0(); } else { CP_WAIT1(); }
        __syncthreads();
        const uint32_t stb = sb + (uint32_t)(kc % 3) * 49152;
        #pragma unroll
        for (int ki = 0; ki < 4; ki++) {
            uint32_t ahf[2][4], alf[2][4], bhf[2][4];
            #pragma unroll
            for (int mi = 0; mi < 2; mi++) {
                uint32_t off = swz(((wm << 5) + (mi << 4) + a_row) * 128 + (ki << 5) + a_kb);
                ldsm4(ahf[mi], stb + off);
                ldsm4(alf[mi], stb + 16384 + off);
            }
            #pragma unroll
            for (int nh = 0; nh < 2; nh++) {
                uint32_t off = swz(((wn << 5) + (nh << 4) + b_row) * 128 + (ki << 5) + b_kb);
                ldsm4(bhf[nh], stb + 32768 + off);
            }
            #pragma unroll
            for (int mi = 0; mi < 2; mi++)
                #pragma unroll
                for (int ni = 0; ni < 4; ni++)
                    mma16816h(acc[mi][ni], ahf[mi], &bhf[ni >> 1][(ni & 1) << 1]);
            #pragma unroll
            for (int mi = 0; mi < 2; mi++)
                #pragma unroll
                for (int ni = 0; ni < 4; ni++)
                    mma16816h(acc[mi][ni], alf[mi], &bhf[ni >> 1][(ni & 1) << 1]);
        }
        if (kc + 2 < 16) issue(kc + 2);
    }

    const int g = lane >> 2, tq = lane & 3;
    #pragma unroll
    for (int mi = 0; mi < 2; mi++) {
        #pragma unroll
        for (int ni = 0; ni < 4; ni++) {
            #pragma unroll
            for (int half = 0; half < 2; half++) {
                int r = (wm << 5) + (mi << 4) + g + half * 8;
                int c = (wn << 5) + (ni << 3) + (tq << 1);
                float v0 = acc[mi][ni][half * 2], v1 = acc[mi][ni][half * 2 + 1];
                int m = m0 + r, n = n0 + c;
                if (mode == 3) {
                    *(float2*)&outp[(size_t)m * 1024 + n] = make_float2(v0, v1);
                } else {
                    int b = m >> 11, s = m & 2047, hd = n >> 6, dk = n & 63;
                    size_t o = (((size_t)(b * 16 + hd) * 2048) + s) * 64 + dk;
                    uint32_t hv = h2(v0, v1);
                    __half* d = (mode == 0) ? g_Q16 : (mode == 1) ? g_K16 : g_V16;
                    *(uint32_t*)(d + o) = hv;
                }
            }
        }
    }
}

// ---------------- fused attention: 64q-tile, two-pass softmax + PV, 512 thr ----
// S = qh . kh (1-term fp16) in BOTH passes; PV 1-term fp16.
// smem: Q16 0 (8K), rowsm 8192 (64f), rinv 8448 (64f),
//       bias s @ 9216+s*1024 (191f), mask s @ 11264+s*512 (128i),
//       stages @ 12288 + s*32768: {K16 +0 (16K), V16 +16384 (16K)}
//       PV-reduce buffer reuses 12288.. (64KB) after last tile.
__global__ __launch_bounds__(512) void attn_fused(const int* __restrict__ mask,
                                                  float* __restrict__ attn) {
    extern __shared__ __align__(1024) char smx[];
    const uint32_t sb = smem_u32(smx);
    float* rowsm = (float*)(smx + 8192);
    float* rinv  = (float*)(smx + 8448);
    const int t = threadIdx.x, lane = t & 31, wid = t >> 5;
    const int wm = wid >> 2, wn = wid & 3;          // wm: q 16-row slice, wn: k 32-slice
    const int q0 = blockIdx.x << 6, bh = blockIdx.y, b = bh >> 4, h = bh & 15;
    const int g = lane >> 2, tq = lane & 3;

    // persistent Q tile: single fp16
    {
        int row = t >> 3, ge = (t & 7) << 3;
        uint32_t so = swz(row * 128 + (ge << 1));
        size_t go = ((size_t)bh * 2048 + q0 + row) * 64 + ge;
        *(uint4*)(smx + so) = *(const uint4*)(g_Q16 + go);
    }
    if (t < 64) rowsm[t] = 0.f;
    __syncthreads();

    const uint32_t a_row = (lane & 7) + ((lane >> 3) & 1) * 8;
    const uint32_t a_kb  = (lane >> 4) * 16;
    const uint32_t b_row = (lane & 7) + (lane >> 4) * 8;
    const uint32_t b_kb  = ((lane >> 3) & 1) * 16;

    // lvl: 0 = K16 only (pass 1), 1 = K16+V16 (pass 2)
    auto issue = [&](int kt, int lvl) {
        const int k0 = kt << 7, s = kt & 1;
        const uint32_t stb = sb + 12288 + (uint32_t)s * 32768;
        #pragma unroll
        for (int i = 0; i < 2; i++) {
            int idx = t + (i << 9);
            int row = idx >> 3, ge = (idx & 7) << 3;
            uint32_t so = swz(row * 128 + (ge << 1));
            size_t go = ((size_t)bh * 2048 + k0 + row) * 64 + ge;
            cpa16(stb + so, g_K16 + go);
            if (lvl) cpa16(stb + 16384 + so, g_V16 + go);
        }
        CP_COMMIT();
        float* bw = (float*)(smx + 9216 + s * 1024);
        int*   ms = (int*)(smx + 11264 + s * 512);
        if (t < 191) bw[t] = g_bias[h * 4096 + (k0 - q0 + 1985) + t];
        if (t < 128) ms[t] = mask[b * 2048 + k0 + t];
    };

    // hoist this warp's Q fragments (16 q-rows, k-invariant)
    uint32_t qf[4][4];
    #pragma unroll
    for (int ki = 0; ki < 4; ki++) {
        uint32_t off = swz(((wm << 4) + a_row) * 128 + (ki << 5) + a_kb);
        ldsm4(qf[ki], sb + off);
    }

    // 1-term S compute
    auto computeS = [&](int stage, float acc[4][4]) {
        const uint32_t kbb = sb + 12288 + (uint32_t)stage * 32768;
        #pragma unroll
        for (int ki = 0; ki < 4; ki++) {
            uint32_t bhf[2][4];
            #pragma unroll
            for (int nh = 0; nh < 2; nh++) {
                uint32_t off = swz(((wn << 5) + (nh << 4) + b_row) * 128 + (ki << 5) + b_kb);
                ldsm4(bhf[nh], kbb + off);
            }
            #pragma unroll
            for (int ni = 0; ni < 4; ni++)
                mma16816h(acc[ni], qf[ki], &bhf[ni >> 1][(ni & 1) << 1]);
        }
    };

    // ---------------- pass 1: row sums ----------------
    {
        float rowpart[2] = {};
        issue(0, 0);
        for (int kt = 0; kt < 16; kt++) {
            if (kt + 1 < 16) { issue(kt + 1, 0); CP_WAIT1(); }
            else             { CP_WAIT0(); }
            __syncthreads();
            float acc[4][4] = {};
            computeS(kt & 1, acc);
            const float* bw = (const float*)(smx + 9216 + (kt & 1) * 1024);
            const int*   ms = (const int*)(smx + 11264 + (kt & 1) * 512);
            #pragma unroll
            for (int half = 0; half < 2; half++) {
                int r = (wm << 4) + g + half * 8;
                float rp = 0.f;
                #pragma unroll
                for (int ni = 0; ni < 4; ni++) {
                    int c = (wn << 5) + (ni << 3) + (tq << 1);
                    float s0 = fmaf(acc[ni][half * 2],     0.125f, bw[c - r + 63]);
                    float s1 = fmaf(acc[ni][half * 2 + 1], 0.125f, bw[c + 1 - r + 63]);
                    rp += (ms[c]     ? __expf(s0) : 0.f);
                    rp += (ms[c + 1] ? __expf(s1) : 0.f);
                }
                rowpart[half] += rp;
            }
            __syncthreads();
        }
        #pragma unroll
        for (int half = 0; half < 2; half++) {
            float v = rowpart[half];
            v += __shfl_xor_sync(0xffffffffu, v, 1);
            v += __shfl_xor_sync(0xffffffffu, v, 2);
            if (tq == 0)
                atomicAdd(&rowsm[(wm << 4) + g + half * 8], v);
        }
    }
    __syncthreads();
    if (t < 64) rinv[t] = 1.0f / rowsm[t];
    __syncthreads();
    float riv[2];
    #pragma unroll
    for (int half = 0; half < 2; half++)
        riv[half] = rinv[(wm << 4) + g + half * 8];

    // ---------------- pass 2: normalized attn store + fp16 PV ----------------
    float pv[8][4] = {};
    issue(0, 1);
    for (int kt = 0; kt < 16; kt++) {
        const int k0 = kt << 7;
        if (kt + 1 < 16) { issue(kt + 1, 1); CP_WAIT1(); }
        else             { CP_WAIT0(); }
        __syncthreads();
        float acc[4][4] = {};
        computeS(kt & 1, acc);
        const float* bw = (const float*)(smx + 9216 + (kt & 1) * 1024);
        const int*   ms = (const int*)(smx + 11264 + (kt & 1) * 512);
        #pragma unroll
        for (int half = 0; half < 2; half++) {
            int r = (wm << 4) + g + half * 8;
            float ri = riv[half];
            #pragma unroll
            for (int ni = 0; ni < 4; ni++) {
                int c = (wn << 5) + (ni << 3) + (tq << 1);
                float s0 = fmaf(acc[ni][half * 2],     0.125f, bw[c - r + 63]);
                float s1 = fmaf(acc[ni][half * 2 + 1], 0.125f, bw[c + 1 - r + 63]);
                float e0 = (ms[c]     ? __expf(s0) : 0.f) * ri;
                float e1 = (ms[c + 1] ? __expf(s1) : 0.f) * ri;
                *(float2*)&attn[((size_t)bh * 2048 + q0 + r) * 2048 + k0 + c] =
                    make_float2(e0, e1);
                acc[ni][half * 2]     = e0;
                acc[ni][half * 2 + 1] = e1;
            }
        }
        // PV: P (fp16) x V (fp16), single term
        const uint32_t vbase = sb + 12288 + (uint32_t)(kt & 1) * 32768 + 16384;
        #pragma unroll
        for (int j = 0; j < 2; j++) {
            uint32_t Ahh[4];
            Ahh[0] = h2(acc[2*j][0],   acc[2*j][1]);
            Ahh[1] = h2(acc[2*j][2],   acc[2*j][3]);
            Ahh[2] = h2(acc[2*j+1][0], acc[2*j+1][1]);
            Ahh[3] = h2(acc[2*j+1][2], acc[2*j+1][3]);
            #pragma unroll
            for (int dvg = 0; dvg < 4; dvg++) {
                uint32_t vf[4];
                uint32_t off = swz(((wn << 5) + (j << 4) + a_row) * 128 + (dvg << 5) + a_kb);
                ldsm4t(vf, vbase + off);
                #pragma unroll
                for (int n8 = 0; n8 < 2; n8++)
                    mma16816h(pv[dvg * 2 + n8], Ahh, &vf[n8 << 1]);
            }
        }
        __syncthreads();
    }

    // ---------------- cross-warp PV reduction + ctx store (fp16 hi/lo) ---------
    #pragma unroll
    for (int ni = 0; ni < 8; ni++)
        #pragma unroll
        for (int half = 0; half < 2; half++) {
            int row = (wm << 4) + g + half * 8;
            uint32_t off = 12288 + (uint32_t)wn * 16384 + row * 256 + ((ni << 3) + (tq << 1)) * 4;
            *(float2*)(smx + off) = make_float2(pv[ni][half * 2], pv[ni][half * 2 + 1]);
        }
    __syncthreads();
    #pragma unroll
    for (int i = 0; i < 4; i++) {
        int idx = t + (i << 9);
        int row = idx >> 5, dvp = idx & 31;
        float sx = 0.f, sy = 0.f;
        #pragma unroll
        for (int w = 0; w < 4; w++) {
            float2 v = *(float2*)(smx + 12288 + w * 16384 + row * 256 + dvp * 8);
            sx += v.x; sy += v.y;
        }
        uint32_t lo, hi = pkh2(sx, sy, lo);
        size_t o = ((size_t)(b * 2048 + q0 + row)) * 1024 + (h << 6) + dvp * 2;
        *(uint32_t*)(g_Ch + o) = hi;
        *(uint32_t*)(g_Cl + o) = lo;
    }
}

// ---------------- launch --------------------------------------------------------
#define PROJ_SMEM 147456
#define ATT_SMEM  77824

extern "C" void kernel_launch(void* const* d_in, const int* in_sizes, int n_in,
                              void* d_out, int out_size) {
    const float* hs   = (const float*)d_in[0];
    const int*   mask = (const int*)d_in[1];
    const float* Wq   = (const float*)d_in[2];
    const float* Wk   = (const float*)d_in[3];
    const float* Wv   = (const float*)d_in[4];
    const float* Wo   = (const float*)d_in[5];
    const float* rb   = (const float*)d_in[6];
    float* out  = (float*)d_out;
    float* attn = out + 4194304;

    cudaFuncSetAttribute(proj_gemm,  cudaFuncAttributeMaxDynamicSharedMemorySize, PROJ_SMEM);
    cudaFuncSetAttribute(attn_fused, cudaFuncAttributeMaxDynamicSharedMemorySize, ATT_SMEM);

    bias_init<<<16, 256>>>(rb);
    split_x<<<4096, 256>>>(hs);
    wsplit<<<dim3(32, 32, 4), dim3(32, 8)>>>(Wq, Wk, Wv, Wo);

    proj_gemm<<<dim3(8, 32, 3), 512, PROJ_SMEM>>>(nullptr, 1);   // Q,K,V fused

    attn_fused<<<dim3(32, 32), 512, ATT_SMEM>>>(mask, attn);     // softmax+attn+ctx

    proj_gemm<<<dim3(8, 32, 1), 512, PROJ_SMEM>>>(out, 0);       // ctx @ Wo
}

// round 16
// speedup vs baseline: 1.5925x; 1.1103x over previous
#include <cuda_runtime.h>
#include <cuda_fp16.h>
#include <cstdint>

// ---------------- scratch (static device arrays; no cudaMalloc) -------------
__device__ __align__(16) __half g_Xh[4194304], g_Xl[4194304];
__device__ __align__(16) __half g_Wh[4][1048576];                // [n][k] fp16
__device__ __align__(16) __half g_Q16[4194304];                  // [bh][s][64]
__device__ __align__(16) __half g_K16[4194304], g_V16[4194304];  // [bh][s][64]
__device__ __align__(16) __half g_Ch[4194304], g_Cl[4194304];    // [m][1024]
__device__ float g_bias[16 * 4096];

// ---------------- helpers -----------------------------------------------------
__device__ __forceinline__ uint32_t smem_u32(const void* p) {
    uint32_t a;
    asm("{ .reg .u64 t; cvta.to.shared.u64 t, %1; cvt.u32.u64 %0, t; }" : "=r"(a) : "l"(p));
    return a;
}
__device__ __forceinline__ uint32_t swz(uint32_t off) { return off ^ ((off >> 3) & 0x70); }

__device__ __forceinline__ void cpa16(uint32_t saddr, const void* g) {
    asm volatile("cp.async.cg.shared.global [%0], [%1], 16;" :: "r"(saddr), "l"(g));
}
#define CP_COMMIT() asm volatile("cp.async.commit_group;" ::: "memory")
#define CP_WAIT1()  asm volatile("cp.async.wait_group 1;" ::: "memory")
#define CP_WAIT0()  asm volatile("cp.async.wait_group 0;" ::: "memory")

__device__ __forceinline__ void ldsm4(uint32_t* r, uint32_t addr) {
    asm volatile("ldmatrix.sync.aligned.m8n8.x4.shared.b16 {%0,%1,%2,%3}, [%4];"
        : "=r"(r[0]), "=r"(r[1]), "=r"(r[2]), "=r"(r[3]) : "r"(addr));
}
__device__ __forceinline__ void ldsm4t(uint32_t* r, uint32_t addr) {
    asm volatile("ldmatrix.sync.aligned.m8n8.x4.trans.shared.b16 {%0,%1,%2,%3}, [%4];"
        : "=r"(r[0]), "=r"(r[1]), "=r"(r[2]), "=r"(r[3]) : "r"(addr));
}
__device__ __forceinline__ void mma16816h(float* d, const uint32_t* a, const uint32_t* b) {
    asm volatile("mma.sync.aligned.m16n8k16.row.col.f32.f16.f16.f32 "
        "{%0,%1,%2,%3}, {%4,%5,%6,%7}, {%8,%9}, {%0,%1,%2,%3};"
        : "+f"(d[0]), "+f"(d[1]), "+f"(d[2]), "+f"(d[3])
        : "r"(a[0]), "r"(a[1]), "r"(a[2]), "r"(a[3]), "r"(b[0]), "r"(b[1]));
}
__device__ __forceinline__ uint32_t h2(float a, float b) {
    __half2 h = __floats2half2_rn(a, b);
    return *(uint32_t*)&h;
}
__device__ __forceinline__ uint32_t pkh2(float a, float b, uint32_t& lo) {
    __half2 h = __floats2half2_rn(a, b);
    __half2 l = __floats2half2_rn(a - __half2float(__low2half(h)),
                                  b - __half2float(__high2half(h)));
    lo = *(uint32_t*)&l;
    return *(uint32_t*)&h;
}

// ---------------- prep kernels -------------------------------------------------
__global__ void bias_init(const float* __restrict__ rel_bias) {
    int d = blockIdx.x * 256 + threadIdx.x;
    if (d >= 4096) return;
    int n = -(d - 2048);
    int ret = 0;
    if (n < 0) { ret = 16; n = -n; }
    int bucket;
    if      (n <  8) bucket = n;
    else if (n < 12) bucket = 8;
    else if (n < 16) bucket = 9;
    else if (n < 23) bucket = 10;
    else if (n < 32) bucket = 11;
    else if (n < 46) bucket = 12;
    else if (n < 64) bucket = 13;
    else if (n < 91) bucket = 14;
    else             bucket = 15;
    bucket += ret;
    #pragma unroll
    for (int h = 0; h < 16; h++)
        g_bias[h * 4096 + d] = rel_bias[bucket * 16 + h];
}

__global__ void split_x(const float* __restrict__ src) {
    size_t i = ((size_t)blockIdx.x * 256 + threadIdx.x) * 4;
    float4 v = *(const float4*)(src + i);
    float x[4] = {v.x, v.y, v.z, v.w};
    #pragma unroll
    for (int j = 0; j < 4; j++) {
        __half hh = __float2half_rn(x[j]);
        g_Xh[i + j] = hh;
        g_Xl[i + j] = __float2half_rn(x[j] - __half2float(hh));
    }
}

__global__ void wsplit(const float* __restrict__ W0, const float* __restrict__ W1,
                       const float* __restrict__ W2, const float* __restrict__ W3) {
    __shared__ float tile[32][33];
    const float* W = blockIdx.z == 0 ? W0 : blockIdx.z == 1 ? W1 : blockIdx.z == 2 ? W2 : W3;
    int n0 = blockIdx.x * 32, k0 = blockIdx.y * 32;
    int tx = threadIdx.x, ty = threadIdx.y;
    #pragma unroll
    for (int j = 0; j < 4; j++)
        tile[ty + j * 8][tx] = W[(size_t)(k0 + ty + j * 8) * 1024 + n0 + tx];
    __syncthreads();
    #pragma unroll
    for (int j = 0; j < 4; j++) {
        float x = tile[tx][ty + j * 8];
        size_t o = (size_t)(n0 + ty + j * 8) * 1024 + k0 + tx;     // [n][k]
        g_Wh[blockIdx.z][o] = __float2half_rn(x);
    }
}

// ---------------- unified 128x128 fp16 2-term GEMM, 2-stage, 2 CTA/SM ----------
__global__ __launch_bounds__(512, 2) void proj_gemm(float* __restrict__ outp, int qkv) {
    extern __shared__ __align__(1024) char smx[];
    const uint32_t sb = smem_u32(smx);
    const int t = threadIdx.x, lane = t & 31, wid = t >> 5;
    const int wm = wid >> 2, wn = wid & 3;         // 4x4 warp grid, 32x32 each
    const int m0 = blockIdx.y << 7, n0 = blockIdx.x << 7;
    const int mode = qkv ? (int)blockIdx.z : 3;
    const __half* Ah = (mode == 3) ? g_Ch : g_Xh;
    const __half* Al = (mode == 3) ? g_Cl : g_Xl;
    const __half* Bh = g_Wh[mode];

    auto issue = [&](int kc) {
        const int kb = kc << 6;
        const uint32_t stb = sb + (uint32_t)(kc & 1) * 49152;
        #pragma unroll
        for (int i = 0; i < 2; i++) {
            int idx = t + (i << 9);
            int row = idx >> 3, ge = (idx & 7) << 3;
            uint32_t so = swz(row * 128 + (ge << 1));
            size_t goa = (size_t)(m0 + row) * 1024 + kb + ge;
            size_t gob = (size_t)(n0 + row) * 1024 + kb + ge;
            cpa16(stb + so,         Ah + goa);
            cpa16(stb + 16384 + so, Al + goa);
            cpa16(stb + 32768 + so, Bh + gob);
        }
        CP_COMMIT();
    };

    const uint32_t a_row = (lane & 7) + ((lane >> 3) & 1) * 8;
    const uint32_t a_kb  = (lane >> 4) * 16;
    const uint32_t b_row = (lane & 7) + (lane >> 4) * 8;
    const uint32_t b_kb  = ((lane >> 3) & 1) * 16;

    float acc[2][4][4] = {};
    issue(0);
    for (int kc = 0; kc < 16; kc++) {
        if (kc + 1 < 16) { issue(kc + 1); CP_WAIT1(); }
        else             { CP_WAIT0(); }
        __syncthreads();
        const uint32_t stb = sb + (uint32_t)(kc & 1) * 49152;
        #pragma unroll
        for (int ki = 0; ki < 4; ki++) {
            uint32_t ahf[2][4], alf[2][4], bhf[2][4];
            #pragma unroll
            for (int mi = 0; mi < 2; mi++) {
                uint32_t off = swz(((wm << 5) + (mi << 4) + a_row) * 128 + (ki << 5) + a_kb);
                ldsm4(ahf[mi], stb + off);
                ldsm4(alf[mi], stb + 16384 + off);
            }
            #pragma unroll
            for (int nh = 0; nh < 2; nh++) {
                uint32_t off = swz(((wn << 5) + (nh << 4) + b_row) * 128 + (ki << 5) + b_kb);
                ldsm4(bhf[nh], stb + 32768 + off);
            }
            #pragma unroll
            for (int mi = 0; mi < 2; mi++)
                #pragma unroll
                for (int ni = 0; ni < 4; ni++)
                    mma16816h(acc[mi][ni], ahf[mi], &bhf[ni >> 1][(ni & 1) << 1]);
            #pragma unroll
            for (int mi = 0; mi < 2; mi++)
                #pragma unroll
                for (int ni = 0; ni < 4; ni++)
                    mma16816h(acc[mi][ni], alf[mi], &bhf[ni >> 1][(ni & 1) << 1]);
        }
        __syncthreads();
    }

    const int g = lane >> 2, tq = lane & 3;
    #pragma unroll
    for (int mi = 0; mi < 2; mi++) {
        #pragma unroll
        for (int ni = 0; ni < 4; ni++) {
            #pragma unroll
            for (int half = 0; half < 2; half++) {
                int r = (wm << 5) + (mi << 4) + g + half * 8;
                int c = (wn << 5) + (ni << 3) + (tq << 1);
                float v0 = acc[mi][ni][half * 2], v1 = acc[mi][ni][half * 2 + 1];
                int m = m0 + r, n = n0 + c;
                if (mode == 3) {
                    *(float2*)&outp[(size_t)m * 1024 + n] = make_float2(v0, v1);
                } else {
                    int b = m >> 11, s = m & 2047, hd = n >> 6, dk = n & 63;
                    size_t o = (((size_t)(b * 16 + hd) * 2048) + s) * 64 + dk;
                    uint32_t hv = h2(v0, v1);
                    __half* d = (mode == 0) ? g_Q16 : (mode == 1) ? g_K16 : g_V16;
                    *(uint32_t*)(d + o) = hv;
                }
            }
        }
    }
}

// ---------------- fused attention: 64q-tile, two-pass, mod-3 ring, 1 sync/tile -
// smem: Q16 0 (8K), rowsm 8192 (64f), rinv 8448 (64f),
//       bias s @ 9216+s*1024 (3 stages), mask s @ 12288+s*512 (3 stages),
//       K/V stages @ 14336 + (s%3)*32768: {K16 +0 (16K), V16 +16384 (16K)}
//       PV-reduce buffer reuses 14336.. (64KB) after last tile.
__global__ __launch_bounds__(512) void attn_fused(const int* __restrict__ mask,
                                                  float* __restrict__ attn) {
    extern __shared__ __align__(1024) char smx[];
    const uint32_t sb = smem_u32(smx);
    float* rowsm = (float*)(smx + 8192);
    float* rinv  = (float*)(smx + 8448);
    const int t = threadIdx.x, lane = t & 31, wid = t >> 5;
    const int wm = wid >> 2, wn = wid & 3;          // wm: q 16-row slice, wn: k 32-slice
    const int q0 = blockIdx.x << 6, bh = blockIdx.y, b = bh >> 4, h = bh & 15;
    const int g = lane >> 2, tq = lane & 3;

    // persistent Q tile: single fp16
    {
        int row = t >> 3, ge = (t & 7) << 3;
        uint32_t so = swz(row * 128 + (ge << 1));
        size_t go = ((size_t)bh * 2048 + q0 + row) * 64 + ge;
        *(uint4*)(smx + so) = *(const uint4*)(g_Q16 + go);
    }
    if (t < 64) rowsm[t] = 0.f;
    __syncthreads();

    const uint32_t a_row = (lane & 7) + ((lane >> 3) & 1) * 8;
    const uint32_t a_kb  = (lane >> 4) * 16;
    const uint32_t b_row = (lane & 7) + (lane >> 4) * 8;
    const uint32_t b_kb  = ((lane >> 3) & 1) * 16;

    // lvl: 0 = K16 only (pass 1), 1 = K16+V16 (pass 2)
    auto issue = [&](int kt, int lvl) {
        const int k0 = kt << 7, s = kt % 3;
        const uint32_t stb = sb + 14336 + (uint32_t)s * 32768;
        #pragma unroll
        for (int i = 0; i < 2; i++) {
            int idx = t + (i << 9);
            int row = idx >> 3, ge = (idx & 7) << 3;
            uint32_t so = swz(row * 128 + (ge << 1));
            size_t go = ((size_t)bh * 2048 + k0 + row) * 64 + ge;
            cpa16(stb + so, g_K16 + go);
            if (lvl) cpa16(stb + 16384 + so, g_V16 + go);
        }
        CP_COMMIT();
        float* bw = (float*)(smx + 9216 + s * 1024);
        int*   ms = (int*)(smx + 12288 + s * 512);
        if (t < 191) bw[t] = g_bias[h * 4096 + (k0 - q0 + 1985) + t];
        if (t < 128) ms[t] = mask[b * 2048 + k0 + t];
    };

    // hoist this warp's Q fragments (16 q-rows, k-invariant)
    uint32_t qf[4][4];
    #pragma unroll
    for (int ki = 0; ki < 4; ki++) {
        uint32_t off = swz(((wm << 4) + a_row) * 128 + (ki << 5) + a_kb);
        ldsm4(qf[ki], sb + off);
    }

    // 1-term S compute from ring stage
    auto computeS = [&](int stage, float acc[4][4]) {
        const uint32_t kbb = sb + 14336 + (uint32_t)stage * 32768;
        #pragma unroll
        for (int ki = 0; ki < 4; ki++) {
            uint32_t bhf[2][4];
            #pragma unroll
            for (int nh = 0; nh < 2; nh++) {
                uint32_t off = swz(((wn << 5) + (nh << 4) + b_row) * 128 + (ki << 5) + b_kb);
                ldsm4(bhf[nh], kbb + off);
            }
            #pragma unroll
            for (int ni = 0; ni < 4; ni++)
                mma16816h(acc[ni], qf[ki], &bhf[ni >> 1][(ni & 1) << 1]);
        }
    };

    // ---------------- pass 1: row sums (mod-3 ring, 1 sync/tile) --------------
    {
        float rowpart[2] = {};
        issue(0, 0); issue(1, 0);
        for (int kt = 0; kt < 16; kt++) {
            if (kt == 15) { CP_WAIT0(); } else { CP_WAIT1(); }
            __syncthreads();
            float acc[4][4] = {};
            computeS(kt % 3, acc);
            const float* bw = (const float*)(smx + 9216 + (kt % 3) * 1024);
            const int*   ms = (const int*)(smx + 12288 + (kt % 3) * 512);
            #pragma unroll
            for (int half = 0; half < 2; half++) {
                int r = (wm << 4) + g + half * 8;
                float rp = 0.f;
                #pragma unroll
                for (int ni = 0; ni < 4; ni++) {
                    int c = (wn << 5) + (ni << 3) + (tq << 1);
                    float s0 = fmaf(acc[ni][half * 2],     0.125f, bw[c - r + 63]);
                    float s1 = fmaf(acc[ni][half * 2 + 1], 0.125f, bw[c + 1 - r + 63]);
                    rp += (ms[c]     ? __expf(s0) : 0.f);
                    rp += (ms[c + 1] ? __expf(s1) : 0.f);
                }
                rowpart[half] += rp;
            }
            if (kt + 2 < 16) issue(kt + 2, 0);
        }
        #pragma unroll
        for (int half = 0; half < 2; half++) {
            float v = rowpart[half];
            v += __shfl_xor_sync(0xffffffffu, v, 1);
            v += __shfl_xor_sync(0xffffffffu, v, 2);
            if (tq == 0)
                atomicAdd(&rowsm[(wm << 4) + g + half * 8], v);
        }
    }
    __syncthreads();
    if (t < 64) rinv[t] = 1.0f / rowsm[t];
    __syncthreads();
    float riv[2];
    #pragma unroll
    for (int half = 0; half < 2; half++)
        riv[half] = rinv[(wm << 4) + g + half * 8];

    // ---------------- pass 2: normalized attn store + fp16 PV -----------------
    float pv[8][4] = {};
    issue(0, 1); issue(1, 1);
    for (int kt = 0; kt < 16; kt++) {
        const int k0 = kt << 7;
        if (kt == 15) { CP_WAIT0(); } else { CP_WAIT1(); }
        __syncthreads();
        float acc[4][4] = {};
        computeS(kt % 3, acc);
        const float* bw = (const float*)(smx + 9216 + (kt % 3) * 1024);
        const int*   ms = (const int*)(smx + 12288 + (kt % 3) * 512);
        #pragma unroll
        for (int half = 0; half < 2; half++) {
            int r = (wm << 4) + g + half * 8;
            float ri = riv[half];
            #pragma unroll
            for (int ni = 0; ni < 4; ni++) {
                int c = (wn << 5) + (ni << 3) + (tq << 1);
                float s0 = fmaf(acc[ni][half * 2],     0.125f, bw[c - r + 63]);
                float s1 = fmaf(acc[ni][half * 2 + 1], 0.125f, bw[c + 1 - r + 63]);
                float e0 = (ms[c]     ? __expf(s0) : 0.f) * ri;
                float e1 = (ms[c + 1] ? __expf(s1) : 0.f) * ri;
                *(float2*)&attn[((size_t)bh * 2048 + q0 + r) * 2048 + k0 + c] =
                    make_float2(e0, e1);
                acc[ni][half * 2]     = e0;
                acc[ni][half * 2 + 1] = e1;
            }
        }
        // PV: P (fp16) x V (fp16), single term
        const uint32_t vbase = sb + 14336 + (uint32_t)(kt % 3) * 32768 + 16384;
        #pragma unroll
        for (int j = 0; j < 2; j++) {
            uint32_t Ahh[4];
            Ahh[0] = h2(acc[2*j][0],   acc[2*j][1]);
            Ahh[1] = h2(acc[2*j][2],   acc[2*j][3]);
            Ahh[2] = h2(acc[2*j+1][0], acc[2*j+1][1]);
            Ahh[3] = h2(acc[2*j+1][2], acc[2*j+1][3]);
            #pragma unroll
            for (int dvg = 0; dvg < 4; dvg++) {
                uint32_t vf[4];
                uint32_t off = swz(((wn << 5) + (j << 4) + a_row) * 128 + (dvg << 5) + a_kb);
                ldsm4t(vf, vbase + off);
                #pragma unroll
                for (int n8 = 0; n8 < 2; n8++)
                    mma16816h(pv[dvg * 2 + n8], Ahh, &vf[n8 << 1]);
            }
        }
        if (kt + 2 < 16) issue(kt + 2, 1);
    }

    // ---------------- cross-warp PV reduction + ctx store (fp16 hi/lo) ---------
    __syncthreads();                                // all PV reads of ring done
    #pragma unroll
    for (int ni = 0; ni < 8; ni++)
        #pragma unroll
        for (int half = 0; half < 2; half++) {
            int row = (wm << 4) + g + half * 8;
            uint32_t off = 14336 + (uint32_t)wn * 16384 + row * 256 + ((ni << 3) + (tq << 1)) * 4;
            *(float2*)(smx + off) = make_float2(pv[ni][half * 2], pv[ni][half * 2 + 1]);
        }
    __syncthreads();
    #pragma unroll
    for (int i = 0; i < 4; i++) {
        int idx = t + (i << 9);
        int row = idx >> 5, dvp = idx & 31;
        float sx = 0.f, sy = 0.f;
        #pragma unroll
        for (int w = 0; w < 4; w++) {
            float2 v = *(float2*)(smx + 14336 + w * 16384 + row * 256 + dvp * 8);
            sx += v.x; sy += v.y;
        }
        uint32_t lo, hi = pkh2(sx, sy, lo);
        size_t o = ((size_t)(b * 2048 + q0 + row)) * 1024 + (h << 6) + dvp * 2;
        *(uint32_t*)(g_Ch + o) = hi;
        *(uint32_t*)(g_Cl + o) = lo;
    }
}

// ---------------- launch --------------------------------------------------------
#define PROJ_SMEM 98304
#define ATT_SMEM  112640

extern "C" void kernel_launch(void* const* d_in, const int* in_sizes, int n_in,
                              void* d_out, int out_size) {
    const float* hs   = (const float*)d_in[0];
    const int*   mask = (const int*)d_in[1];
    const float* Wq   = (const float*)d_in[2];
    const float* Wk   = (const float*)d_in[3];
    const float* Wv   = (const float*)d_in[4];
    const float* Wo   = (const float*)d_in[5];
    const float* rb   = (const float*)d_in[6];
    float* out  = (float*)d_out;
    float* attn = out + 4194304;

    cudaFuncSetAttribute(proj_gemm,  cudaFuncAttributeMaxDynamicSharedMemorySize, PROJ_SMEM);
    cudaFuncSetAttribute(attn_fused, cudaFuncAttributeMaxDynamicSharedMemorySize, ATT_SMEM);

    bias_init<<<16, 256>>>(rb);
    split_x<<<4096, 256>>>(hs);
    wsplit<<<dim3(32, 32, 4), dim3(32, 8)>>>(Wq, Wk, Wv, Wo);

    proj_gemm<<<dim3(8, 32, 3), 512, PROJ_SMEM>>>(nullptr, 1);   // Q,K,V fused

    attn_fused<<<dim3(32, 32), 512, ATT_SMEM>>>(mask, attn);     // softmax+attn+ctx

    proj_gemm<<<dim3(8, 32, 1), 512, PROJ_SMEM>>>(out, 0);       // ctx @ Wo
}